// round 11
// baseline (speedup 1.0000x reference)
#include <cuda_runtime.h>
#include <cuda_bf16.h>
#include <cuda_fp16.h>
#include <cstdint>

#define TILEM 128
#define NTHR  256
#define ARS   144      // smem row stride (bytes)

// smem byte offsets
#define SM_R0    0
#define SM_R1    18432
#define SM_W     36864   // 36864B: chain bufA@0, bufB@18432 (hi+lo 9216 each); heavy chunks c*9216
#define SM_WTAIL 73728
#define SM_MASK  75776
#define SM_TOTAL 76288

// chain weights (fp16 hi/lo 2-term, [n][k] 64x64), slots: 0=Wd1 1=Wd2 2=Wp1 3=Wu1 4=Wu2 5=Wu3
__device__ __align__(16) __half g_wh[6 * 4096];
__device__ __align__(16) __half g_wl[6 * 4096];
// heavy weights (fp16 single, [n][k] 64x64), chunks: 0-3 = Wp2, 4-11 = Wu4
__device__ __align__(16) __half g_wx[12 * 4096];
__device__ __align__(16) float g_bb[18 * 64];
__device__ __align__(16) float g_aw[18 * 64];
__device__ int g_inv[(size_t)262144 * 8];

static __device__ __forceinline__ uint32_t smem_u32(const void* p) {
    uint32_t a;
    asm("{ .reg .u64 t; cvta.to.shared.u64 t, %1; cvt.u32.u64 %0, t; }" : "=r"(a) : "l"(p));
    return a;
}
static __device__ __forceinline__ uint32_t pk_half2(float a, float b) {
    __half2 t = __floats2half2_rn(a, b);
    return *(uint32_t*)&t;
}
static __device__ __forceinline__ float2 upk_half2(uint32_t u) {
    return __half22float2(*(__half2*)&u);
}
static __device__ __forceinline__ void mma_f16(float* c, const uint32_t* a, const uint32_t* b) {
    asm volatile(
        "mma.sync.aligned.m16n8k16.row.col.f32.f16.f16.f32 "
        "{%0,%1,%2,%3}, {%4,%5,%6,%7}, {%8,%9}, {%0,%1,%2,%3};"
        : "+f"(c[0]), "+f"(c[1]), "+f"(c[2]), "+f"(c[3])
        : "r"(a[0]), "r"(a[1]), "r"(a[2]), "r"(a[3]), "r"(b[0]), "r"(b[1]));
}
static __device__ __forceinline__ void ldm4(uint32_t* r, uint32_t addr) {
    asm volatile("ldmatrix.sync.aligned.m8n8.x4.shared.b16 {%0,%1,%2,%3}, [%4];"
        : "=r"(r[0]), "=r"(r[1]), "=r"(r[2]), "=r"(r[3]) : "r"(addr));
}
static __device__ __forceinline__ void zero_acc(float acc[2][4][4]) {
#pragma unroll
    for (int mt = 0; mt < 2; mt++)
#pragma unroll
        for (int nt = 0; nt < 4; nt++)
#pragma unroll
            for (int i = 0; i < 4; i++) acc[mt][nt][i] = 0.f;
}

// chain GEMM: A single fp16, W 2-term fp16 (Wh+Wl); warp tile m32 x n32
static __device__ __forceinline__ void chain_gemm(uint32_t aB, uint32_t wHb, uint32_t wLb,
                                                  float acc[2][4][4]) {
#pragma unroll
    for (int kc = 0; kc < 4; kc++) {
        uint32_t ko = kc * 32;
        uint32_t a2[2][4], bh[2][4], bl[2][4];
        ldm4(a2[0], aB + ko); ldm4(a2[1], aB + ko + 16 * ARS);
        ldm4(bh[0], wHb + ko); ldm4(bh[1], wHb + ko + 16 * ARS);
        ldm4(bl[0], wLb + ko); ldm4(bl[1], wLb + ko + 16 * ARS);
#pragma unroll
        for (int p2 = 0; p2 < 2; p2++)
#pragma unroll
            for (int h = 0; h < 2; h++) {
                int nt = p2 * 2 + h;
                const uint32_t* Bh = &bh[p2][h * 2];
                const uint32_t* Bl = &bl[p2][h * 2];
#pragma unroll
                for (int mt = 0; mt < 2; mt++) {
                    mma_f16(acc[mt][nt], a2[mt], Bh);
                    mma_f16(acc[mt][nt], a2[mt], Bl);
                }
            }
    }
}
// heavy GEMM: A single fp16 (from smem), W single fp16
static __device__ __forceinline__ void heavy_gemm(uint32_t aB, uint32_t wb, float acc[2][4][4]) {
#pragma unroll
    for (int kc = 0; kc < 4; kc++) {
        uint32_t ko = kc * 32;
        uint32_t a2[2][4], bh[2][4];
        ldm4(a2[0], aB + ko); ldm4(a2[1], aB + ko + 16 * ARS);
        ldm4(bh[0], wb + ko); ldm4(bh[1], wb + ko + 16 * ARS);
#pragma unroll
        for (int p2 = 0; p2 < 2; p2++)
#pragma unroll
            for (int h = 0; h < 2; h++) {
                int nt = p2 * 2 + h;
                const uint32_t* Bh = &bh[p2][h * 2];
#pragma unroll
                for (int mt = 0; mt < 2; mt++)
                    mma_f16(acc[mt][nt], a2[mt], Bh);
            }
    }
}

static __device__ __forceinline__ void add_bias(float acc[2][4][4], int j, int ncol, int tg) {
    const float* bb = g_bb + j * 64;
#pragma unroll
    for (int nt = 0; nt < 4; nt++) {
        float2 bv = __ldg((const float2*)(bb + ncol + nt * 8 + tg * 2));
#pragma unroll
        for (int mt = 0; mt < 2; mt++) {
            float* c = acc[mt][nt];
            c[0] += bv.x; c[1] += bv.y; c[2] += bv.x; c[3] += bv.y;
        }
    }
}
static __device__ __forceinline__ void apply_prelu(float acc[2][4][4], int j, int ncol, int tg) {
    const float* aw = g_aw + j * 64;
#pragma unroll
    for (int nt = 0; nt < 4; nt++) {
        float2 av = __ldg((const float2*)(aw + ncol + nt * 8 + tg * 2));
#pragma unroll
        for (int mt = 0; mt < 2; mt++) {
            float* c = acc[mt][nt];
            c[0] = c[0] >= 0.f ? c[0] : av.x * c[0];
            c[1] = c[1] >= 0.f ? c[1] : av.y * c[1];
            c[2] = c[2] >= 0.f ? c[2] : av.x * c[2];
            c[3] = c[3] >= 0.f ? c[3] : av.y * c[3];
        }
    }
}
static __device__ __forceinline__ void add_residual(const char* rgn, float acc[2][4][4],
                                                    int mrow, int g, int ncol, int tg) {
#pragma unroll
    for (int mt = 0; mt < 2; mt++) {
        int r = mrow + mt * 16 + g;
#pragma unroll
        for (int nt = 0; nt < 4; nt++) {
            uint32_t off0 = r * ARS + (ncol + nt * 8 + tg * 2) * 2;
            uint32_t off1 = off0 + 8 * ARS;
            float2 v0 = upk_half2(*(const uint32_t*)(rgn + off0));
            float2 v1 = upk_half2(*(const uint32_t*)(rgn + off1));
            float* c = acc[mt][nt];
            c[0] += v0.x; c[1] += v0.y; c[2] += v1.x; c[3] += v1.y;
        }
    }
}
static __device__ __forceinline__ void store_f16(char* dst, float acc[2][4][4],
                                                 int mrow, int g, int ncol, int tg) {
#pragma unroll
    for (int mt = 0; mt < 2; mt++) {
        int r = mrow + mt * 16 + g;
#pragma unroll
        for (int nt = 0; nt < 4; nt++) {
            uint32_t off0 = r * ARS + (ncol + nt * 8 + tg * 2) * 2;
            uint32_t off1 = off0 + 8 * ARS;
            float* c = acc[mt][nt];
            *(uint32_t*)(dst + off0) = pk_half2(c[0], c[1]);
            *(uint32_t*)(dst + off1) = pk_half2(c[2], c[3]);
        }
    }
}

// ---------------- K_prep ----------------
__global__ void k_prep(const float* __restrict__ Wd1, const float* __restrict__ Wd2,
                       const float* __restrict__ Wp1, const float* __restrict__ Wp2,
                       const float* __restrict__ Wu1, const float* __restrict__ Wu2,
                       const float* __restrict__ Wu3, const float* __restrict__ Wu4,
                       const float* __restrict__ bd1, const float* __restrict__ bd2,
                       const float* __restrict__ bp1, const float* __restrict__ bp2,
                       const float* __restrict__ bu1, const float* __restrict__ bu2,
                       const float* __restrict__ bu3, const float* __restrict__ bu4,
                       const float* __restrict__ ad,  const float* __restrict__ ap_,
                       const float* __restrict__ au1, const float* __restrict__ au2) {
    int j = blockIdx.x;
    int slot = (j == 0) ? 0 : (j == 1) ? 1 : (j == 2) ? 2 :
               (j == 7) ? 3 : (j == 8) ? 4 : (j == 9) ? 5 : -1;
    for (int t = threadIdx.x; t < 4096; t += 256) {
        int n = t >> 6, k = t & 63;
        float v;
        if (j == 0)      v = Wd1[k * 64 + n];
        else if (j == 1) v = Wd2[k * 64 + n];
        else if (j == 2) v = Wp1[k * 64 + n];
        else if (j <= 6) { int ng = (j - 3) * 64 + n; v = (ng < 255) ? Wp2[k * 255 + ng] : 0.f; }
        else if (j == 7) v = Wu1[k * 64 + n];
        else if (j == 8) v = Wu2[k * 64 + n];
        else if (j == 9) v = Wu3[k * 64 + n];
        else             v = Wu4[(size_t)k * 512 + (j - 10) * 64 + n];
        if (slot >= 0) {
            __half h = __float2half(v);
            __half l = __float2half(v - __half2float(h));
            g_wh[slot * 4096 + t] = h;
            g_wl[slot * 4096 + t] = l;
        } else {
            int ch = (j <= 6) ? (j - 3) : (4 + j - 10);
            g_wx[ch * 4096 + n * 64 + k] = __float2half(v);
        }
    }
    int t = threadIdx.x;
    if (t < 64) {
        int c = t; float b = 0.f, a = 0.f;
        switch (j) {
            case 0: b = bd1[c]; a = ad[c]; break;
            case 1: b = bd2[c]; break;
            case 2: b = bp1[c]; a = ap_[c]; break;
            case 3: case 4: case 5: case 6: {
                int ng = (j - 3) * 64 + c; b = (ng < 255) ? bp2[ng] : 0.f; break; }
            case 7: b = bu1[c]; a = au1[c]; break;
            case 8: b = bu2[c]; a = au2[c]; break;
            case 9: b = bu3[c]; break;
            default: b = bu4[(j - 10) * 64 + c]; break;
        }
        g_bb[j * 64 + c] = b;
        g_aw[j * 64 + c] = a;
    }
}

// ---------------- K0: inverse map ----------------
__global__ void k0_inv(const int* __restrict__ sel, int M) {
    int m = blockIdx.x * 256 + threadIdx.x;
    if (m < M) g_inv[sel[m]] = m;
}

// ---------------- fused main kernel ----------------
__global__ __launch_bounds__(NTHR, 3)
void k_main(const float* __restrict__ X, const int* __restrict__ bin,
            const float* __restrict__ Wu1,
            float* __restrict__ pred, float* __restrict__ oct, float* __restrict__ newF) {
    extern __shared__ char smem[];
    const uint32_t sb = smem_u32(smem);
    int tid = threadIdx.x;
    int wid = tid >> 5, lane = tid & 31;
    int g = lane >> 2, tg = lane & 3;
    int mrow = (wid >> 1) * 32;
    int ncol = (wid & 1) * 32;
    int base = blockIdx.x * TILEM;

    float* wtail = (float*)(smem + SM_WTAIL);
    int*   smask = (int*)(smem + SM_MASK);

    // ---- prologue: X -> R0 fp16, mask/oct, wtail ----
    {
        const float4* Xr = (const float4*)(X + (size_t)base * 64);
#pragma unroll
        for (int it = 0; it < 8; it++) {
            int idx = it * NTHR + tid;
            int row = idx >> 4, q = idx & 15;
            float4 v = Xr[idx];
            *(uint2*)(smem + SM_R0 + row * ARS + q * 8) =
                make_uint2(pk_half2(v.x, v.y), pk_half2(v.z, v.w));
        }
        if (tid < TILEM) {
            const int* bp = bin + (size_t)(base + tid) * 8;
            int4 b0 = *(const int4*)bp;
            int4 b1 = *(const int4*)(bp + 4);
            int m = (b0.x != 0) | ((b0.y != 0) << 1) | ((b0.z != 0) << 2) | ((b0.w != 0) << 3)
                  | ((b1.x != 0) << 4) | ((b1.y != 0) << 5) | ((b1.z != 0) << 6) | ((b1.w != 0) << 7);
            smask[tid] = m;
            oct[base + tid] = (float)(m - 1);
        }
#pragma unroll
        for (int it = 0; it < 2; it++)
            wtail[it * NTHR + tid] = Wu1[4096 + it * NTHR + tid];
    }

    uint4 wr0, wr1, wr2, wr3;
    auto prefetchW = [&](int slot) {
        const uint4* sh = (const uint4*)(g_wh + slot * 4096);
        const uint4* sl = (const uint4*)(g_wl + slot * 4096);
        wr0 = sh[tid]; wr1 = sh[tid + 256];
        wr2 = sl[tid]; wr3 = sl[tid + 256];
    };
    auto commitW = [&](int buf) {   // hi at base, lo at base+9216
        char* b = smem + SM_W + buf * 18432;
        int i0 = tid, i1 = tid + 256;
        *(uint4*)(b + (i0 >> 3) * ARS + (i0 & 7) * 16)        = wr0;
        *(uint4*)(b + (i1 >> 3) * ARS + (i1 & 7) * 16)        = wr1;
        *(uint4*)(b + 9216 + (i0 >> 3) * ARS + (i0 & 7) * 16) = wr2;
        *(uint4*)(b + 9216 + (i1 >> 3) * ARS + (i1 & 7) * 16) = wr3;
    };

    uint32_t aoff = (uint32_t)((mrow + (lane & 7) + ((lane >> 3) & 1) * 8) * ARS
                              + ((lane >> 4) & 1) * 16);
    uint32_t woff = (uint32_t)((ncol + (lane & 7) + ((lane >> 4) & 1) * 8) * ARS
                              + ((lane >> 3) & 1) * 16);

    float acc[2][4][4];

    prefetchW(0);
    commitW(0);
    __syncthreads();          // prologue + W0 visible
    prefetchW(1);

    // ---- j0: h = prelu(X@Wd1+b) -> R1 fp16 ----
    zero_acc(acc);
    chain_gemm(sb + SM_R0 + aoff, sb + SM_W + woff, sb + SM_W + 9216 + woff, acc);
    add_bias(acc, 0, ncol, tg);
    apply_prelu(acc, 0, ncol, tg);
    store_f16(smem + SM_R1, acc, mrow, g, ncol, tg);
    __syncthreads();
    commitW(1);               // W_j1
    __syncthreads();
    prefetchW(2);

    // ---- j1: rec = X + h@Wd2 + b -> R0 ----
    zero_acc(acc);
    chain_gemm(sb + SM_R1 + aoff, sb + SM_W + 18432 + woff, sb + SM_W + 27648 + woff, acc);
    add_bias(acc, 1, ncol, tg);
    add_residual(smem + SM_R0, acc, mrow, g, ncol, tg);
    store_f16(smem + SM_R0, acc, mrow, g, ncol, tg);
    __syncthreads();
    commitW(0);               // W_j2
    __syncthreads();

    // ---- j2: p = prelu(rec@Wp1+b) -> R1 ----
    zero_acc(acc);
    chain_gemm(sb + SM_R0 + aoff, sb + SM_W + woff, sb + SM_W + 9216 + woff, acc);
    add_bias(acc, 2, ncol, tg);
    apply_prelu(acc, 2, ncol, tg);
    store_f16(smem + SM_R1, acc, mrow, g, ncol, tg);
    __syncthreads();

    // ---- stage pred W (4 chunks into full W region) + prefetch Wu1 ----
    {
        const uint4* src = (const uint4*)g_wx;
#pragma unroll
        for (int it = 0; it < 8; it++) {
            int i = it * NTHR + tid;            // 0..2047 uint4
            int c = i >> 9, w = i & 511;
            *(uint4*)(smem + SM_W + c * 9216 + (w >> 3) * ARS + (w & 7) * 16) = src[i];
        }
    }
    prefetchW(3);
    __syncthreads();

    // ---- pred group: 4 sync-free chunks (A = p in R1) ----
#pragma unroll
    for (int c = 0; c < 4; c++) {
        zero_acc(acc);
        heavy_gemm(sb + SM_R1 + aoff, sb + SM_W + c * 9216 + woff, acc);
        add_bias(acc, 3 + c, ncol, tg);
        int o0 = c * 64;
#pragma unroll
        for (int mt = 0; mt < 2; mt++) {
            int r = base + mrow + mt * 16 + g;
#pragma unroll
            for (int nt = 0; nt < 4; nt++) {
                int col = o0 + ncol + nt * 8 + tg * 2;
                float* cc = acc[mt][nt];
                float* p0 = pred + (size_t)r * 255 + col;
                float* p1 = pred + (size_t)(r + 8) * 255 + col;
                if (col < 255) { p0[0] = cc[0]; p1[0] = cc[2]; }
                if (col + 1 < 255) { p0[1] = cc[1]; p1[1] = cc[3]; }
            }
        }
    }
    __syncthreads();
    commitW(0);               // W_j7
    __syncthreads();
    prefetchW(4);

    // ---- j7: u1 = prelu([rec,bin]@Wu1+b) -> R1 ----
    zero_acc(acc);
    chain_gemm(sb + SM_R0 + aoff, sb + SM_W + woff, sb + SM_W + 9216 + woff, acc);
    add_bias(acc, 7, ncol, tg);
    {   // bin-concat tail (exact fp32)
#pragma unroll
        for (int mt = 0; mt < 2; mt++) {
            int rA = mrow + mt * 16 + g;
            int mA = smask[rA], mB = smask[rA + 8];
#pragma unroll
            for (int jj = 0; jj < 8; jj++) {
                bool bA = (mA >> jj) & 1, bB = (mB >> jj) & 1;
                if (bA | bB) {
#pragma unroll
                    for (int nt = 0; nt < 4; nt++) {
                        float2 t = *(const float2*)(wtail + jj * 64 + ncol + nt * 8 + tg * 2);
                        float* c = acc[mt][nt];
                        if (bA) { c[0] += 256.f * t.x; c[1] += 256.f * t.y; }
                        if (bB) { c[2] += 256.f * t.x; c[3] += 256.f * t.y; }
                    }
                }
            }
        }
    }
    apply_prelu(acc, 7, ncol, tg);
    store_f16(smem + SM_R1, acc, mrow, g, ncol, tg);
    __syncthreads();
    commitW(1);               // W_j8
    __syncthreads();
    prefetchW(5);

    // ---- j8: h2 = prelu(u1@Wu2+b) -> R0 (rec dead) ----
    zero_acc(acc);
    chain_gemm(sb + SM_R1 + aoff, sb + SM_W + 18432 + woff, sb + SM_W + 27648 + woff, acc);
    add_bias(acc, 8, ncol, tg);
    apply_prelu(acc, 8, ncol, tg);
    store_f16(smem + SM_R0, acc, mrow, g, ncol, tg);
    __syncthreads();
    commitW(0);               // W_j9
    __syncthreads();

    // ---- j9: u = u1 + h2@Wu3 + b -> R1 ----
    zero_acc(acc);
    chain_gemm(sb + SM_R0 + aoff, sb + SM_W + woff, sb + SM_W + 9216 + woff, acc);
    add_bias(acc, 9, ncol, tg);
    add_residual(smem + SM_R1, acc, mrow, g, ncol, tg);
    store_f16(smem + SM_R1, acc, mrow, g, ncol, tg);
    __syncthreads();

    // ---- stage up4 chunks 0-5 (0-3 -> W region, 4-5 -> R0) ----
    {
        const uint4* src = (const uint4*)(g_wx + 4 * 4096);
#pragma unroll
        for (int it = 0; it < 12; it++) {
            int i = it * NTHR + tid;            // 0..3071 uint4 (6 chunks)
            int c = i >> 9, w = i & 511;
            uint32_t dst = (c < 4) ? (uint32_t)(SM_W + c * 9216)
                                   : (uint32_t)(SM_R0 + (c - 4) * 9216);
            *(uint4*)(smem + dst + (w >> 3) * ARS + (w & 7) * 16) = src[i];
        }
    }
    __syncthreads();

    // ---- up4 chunks 0-5 (sync-free), then restage 6-7 ----
    auto up4_chunk = [&](int c, uint32_t wb) {
        zero_acc(acc);
        heavy_gemm(sb + SM_R1 + aoff, wb + woff, acc);
        add_bias(acc, 10 + c, ncol, tg);
#pragma unroll
        for (int mt = 0; mt < 2; mt++) {
            int rA = mrow + mt * 16 + g;
            bool okA = (smask[rA] >> c) & 1, okB = (smask[rA + 8] >> c) & 1;
            int iA = okA ? __ldg(&g_inv[(size_t)(base + rA) * 8 + c]) : 0;
            int iB = okB ? __ldg(&g_inv[(size_t)(base + rA + 8) * 8 + c]) : 0;
#pragma unroll
            for (int nt = 0; nt < 4; nt++) {
                int col = ncol + nt * 8 + tg * 2;
                float* cc = acc[mt][nt];
                if (okA) *(float2*)(newF + (size_t)iA * 64 + col) = make_float2(cc[0], cc[1]);
                if (okB) *(float2*)(newF + (size_t)iB * 64 + col) = make_float2(cc[2], cc[3]);
            }
        }
    };
#pragma unroll
    for (int c = 0; c < 4; c++) up4_chunk(c, sb + SM_W + c * 9216);
    up4_chunk(4, sb + SM_R0);
    up4_chunk(5, sb + SM_R0 + 9216);
    __syncthreads();
    {
        const uint4* src = (const uint4*)(g_wx + 10 * 4096);   // chunks 6,7
#pragma unroll
        for (int it = 0; it < 4; it++) {
            int i = it * NTHR + tid;            // 0..1023 uint4
            int c = i >> 9, w = i & 511;
            *(uint4*)(smem + SM_W + c * 9216 + (w >> 3) * ARS + (w & 7) * 16) = src[i];
        }
    }
    __syncthreads();
    up4_chunk(6, sb + SM_W);
    up4_chunk(7, sb + SM_W + 9216);
}

extern "C" void kernel_launch(void* const* d_in, const int* in_sizes, int n_in,
                              void* d_out, int out_size) {
    const float* X   = (const float*)d_in[0];
    const int*   bin = (const int*)d_in[1];
    const int*   sel = (const int*)d_in[2];
    const float* Wd1 = (const float*)d_in[3];
    const float* bd1 = (const float*)d_in[4];
    const float* ad  = (const float*)d_in[5];
    const float* Wd2 = (const float*)d_in[6];
    const float* bd2 = (const float*)d_in[7];
    const float* Wp1 = (const float*)d_in[8];
    const float* bp1 = (const float*)d_in[9];
    const float* ap  = (const float*)d_in[10];
    const float* Wp2 = (const float*)d_in[11];
    const float* bp2 = (const float*)d_in[12];
    const float* Wu1 = (const float*)d_in[13];
    const float* bu1 = (const float*)d_in[14];
    const float* au1 = (const float*)d_in[15];
    const float* Wu2 = (const float*)d_in[16];
    const float* bu2 = (const float*)d_in[17];
    const float* au2 = (const float*)d_in[18];
    const float* Wu3 = (const float*)d_in[19];
    const float* bu3 = (const float*)d_in[20];
    const float* Wu4 = (const float*)d_in[21];
    const float* bu4 = (const float*)d_in[22];

    int n = in_sizes[0] / 64;
    int M = in_sizes[2];
    float* newF = (float*)d_out;
    float* pred = newF + (size_t)M * 64;
    float* oct  = pred + (size_t)n * 255;

    cudaFuncSetAttribute(k_main, cudaFuncAttributeMaxDynamicSharedMemorySize, SM_TOTAL);

    k_prep<<<18, 256>>>(Wd1, Wd2, Wp1, Wp2, Wu1, Wu2, Wu3, Wu4,
                        bd1, bd2, bp1, bp2, bu1, bu2, bu3, bu4,
                        ad, ap, au1, au2);
    if (M > 0) k0_inv<<<(M + 255) / 256, 256>>>(sel, M);
    k_main<<<n / TILEM, NTHR, SM_TOTAL>>>(X, bin, Wu1, pred, oct, newF);
}

// round 12
// speedup vs baseline: 1.1619x; 1.1619x over previous
#include <cuda_runtime.h>
#include <cuda_bf16.h>
#include <cuda_fp16.h>
#include <cstdint>

#define TILEM 128
#define NTHR  256
#define ARS   144      // smem row stride (bytes)

// smem byte offsets
#define SM_R0    0
#define SM_R1    18432
#define SM_W     36864   // chain bufA@0, bufB@18432 (hi+lo 9216 each); heavy chunks c*9216
#define SM_WTAIL 73728
#define SM_MASK  75776
#define SM_TOTAL 76288

// chain weights (fp16 hi/lo 2-term, [n][k] 64x64), slots: 0=Wd1 1=Wd2 2=Wp1 3=Wu1 4=Wu2 5=Wu3
__device__ __align__(16) __half g_wh[6 * 4096];
__device__ __align__(16) __half g_wl[6 * 4096];
// heavy weights (fp16 single, [n][k] 64x64), chunks: 0-3 = Wp2, 4-11 = Wu4
__device__ __align__(16) __half g_wx[12 * 4096];
__device__ __align__(16) float g_bb[18 * 64];
__device__ __align__(16) float g_aw[18 * 64];
__device__ int g_inv[(size_t)262144 * 8];

static __device__ __forceinline__ uint32_t smem_u32(const void* p) {
    uint32_t a;
    asm("{ .reg .u64 t; cvta.to.shared.u64 t, %1; cvt.u32.u64 %0, t; }" : "=r"(a) : "l"(p));
    return a;
}
static __device__ __forceinline__ uint32_t pk_half2(float a, float b) {
    __half2 t = __floats2half2_rn(a, b);
    return *(uint32_t*)&t;
}
static __device__ __forceinline__ float2 upk_half2(uint32_t u) {
    return __half22float2(*(__half2*)&u);
}
static __device__ __forceinline__ void mma_f16(float* c, const uint32_t* a, const uint32_t* b) {
    asm volatile(
        "mma.sync.aligned.m16n8k16.row.col.f32.f16.f16.f32 "
        "{%0,%1,%2,%3}, {%4,%5,%6,%7}, {%8,%9}, {%0,%1,%2,%3};"
        : "+f"(c[0]), "+f"(c[1]), "+f"(c[2]), "+f"(c[3])
        : "r"(a[0]), "r"(a[1]), "r"(a[2]), "r"(a[3]), "r"(b[0]), "r"(b[1]));
}
static __device__ __forceinline__ void ldm4(uint32_t* r, uint32_t addr) {
    asm volatile("ldmatrix.sync.aligned.m8n8.x4.shared.b16 {%0,%1,%2,%3}, [%4];"
        : "=r"(r[0]), "=r"(r[1]), "=r"(r[2]), "=r"(r[3]) : "r"(addr));
}
static __device__ __forceinline__ void zero_acc(float acc[2][4][4]) {
#pragma unroll
    for (int mt = 0; mt < 2; mt++)
#pragma unroll
        for (int nt = 0; nt < 4; nt++)
#pragma unroll
            for (int i = 0; i < 4; i++) acc[mt][nt][i] = 0.f;
}

// chain GEMM: A single fp16, W 2-term fp16 (Wh+Wl); warp tile m32 x n32
static __device__ __forceinline__ void chain_gemm(uint32_t aB, uint32_t wHb, uint32_t wLb,
                                                  float acc[2][4][4]) {
#pragma unroll
    for (int kc = 0; kc < 4; kc++) {
        uint32_t ko = kc * 32;
        uint32_t a2[2][4], bh[2][4], bl[2][4];
        ldm4(a2[0], aB + ko); ldm4(a2[1], aB + ko + 16 * ARS);
        ldm4(bh[0], wHb + ko); ldm4(bh[1], wHb + ko + 16 * ARS);
        ldm4(bl[0], wLb + ko); ldm4(bl[1], wLb + ko + 16 * ARS);
#pragma unroll
        for (int p2 = 0; p2 < 2; p2++)
#pragma unroll
            for (int h = 0; h < 2; h++) {
                int nt = p2 * 2 + h;
                const uint32_t* Bh = &bh[p2][h * 2];
                const uint32_t* Bl = &bl[p2][h * 2];
#pragma unroll
                for (int mt = 0; mt < 2; mt++) {
                    mma_f16(acc[mt][nt], a2[mt], Bh);
                    mma_f16(acc[mt][nt], a2[mt], Bl);
                }
            }
    }
}
// heavy GEMM: A single fp16 (from smem), W single fp16
static __device__ __forceinline__ void heavy_gemm(uint32_t aB, uint32_t wb, float acc[2][4][4]) {
#pragma unroll
    for (int kc = 0; kc < 4; kc++) {
        uint32_t ko = kc * 32;
        uint32_t a2[2][4], bh[2][4];
        ldm4(a2[0], aB + ko); ldm4(a2[1], aB + ko + 16 * ARS);
        ldm4(bh[0], wb + ko); ldm4(bh[1], wb + ko + 16 * ARS);
#pragma unroll
        for (int p2 = 0; p2 < 2; p2++)
#pragma unroll
            for (int h = 0; h < 2; h++) {
                int nt = p2 * 2 + h;
                const uint32_t* Bh = &bh[p2][h * 2];
#pragma unroll
                for (int mt = 0; mt < 2; mt++)
                    mma_f16(acc[mt][nt], a2[mt], Bh);
            }
    }
}

static __device__ __forceinline__ void add_bias(float acc[2][4][4], int j, int ncol, int tg) {
    const float* bb = g_bb + j * 64;
#pragma unroll
    for (int nt = 0; nt < 4; nt++) {
        float2 bv = __ldg((const float2*)(bb + ncol + nt * 8 + tg * 2));
#pragma unroll
        for (int mt = 0; mt < 2; mt++) {
            float* c = acc[mt][nt];
            c[0] += bv.x; c[1] += bv.y; c[2] += bv.x; c[3] += bv.y;
        }
    }
}
static __device__ __forceinline__ void apply_prelu(float acc[2][4][4], int j, int ncol, int tg) {
    const float* aw = g_aw + j * 64;
#pragma unroll
    for (int nt = 0; nt < 4; nt++) {
        float2 av = __ldg((const float2*)(aw + ncol + nt * 8 + tg * 2));
#pragma unroll
        for (int mt = 0; mt < 2; mt++) {
            float* c = acc[mt][nt];
            c[0] = c[0] >= 0.f ? c[0] : av.x * c[0];
            c[1] = c[1] >= 0.f ? c[1] : av.y * c[1];
            c[2] = c[2] >= 0.f ? c[2] : av.x * c[2];
            c[3] = c[3] >= 0.f ? c[3] : av.y * c[3];
        }
    }
}
static __device__ __forceinline__ void add_residual(const char* rgn, float acc[2][4][4],
                                                    int mrow, int g, int ncol, int tg) {
#pragma unroll
    for (int mt = 0; mt < 2; mt++) {
        int r = mrow + mt * 16 + g;
#pragma unroll
        for (int nt = 0; nt < 4; nt++) {
            uint32_t off0 = r * ARS + (ncol + nt * 8 + tg * 2) * 2;
            uint32_t off1 = off0 + 8 * ARS;
            float2 v0 = upk_half2(*(const uint32_t*)(rgn + off0));
            float2 v1 = upk_half2(*(const uint32_t*)(rgn + off1));
            float* c = acc[mt][nt];
            c[0] += v0.x; c[1] += v0.y; c[2] += v1.x; c[3] += v1.y;
        }
    }
}
static __device__ __forceinline__ void store_f16(char* dst, float acc[2][4][4],
                                                 int mrow, int g, int ncol, int tg) {
#pragma unroll
    for (int mt = 0; mt < 2; mt++) {
        int r = mrow + mt * 16 + g;
#pragma unroll
        for (int nt = 0; nt < 4; nt++) {
            uint32_t off0 = r * ARS + (ncol + nt * 8 + tg * 2) * 2;
            uint32_t off1 = off0 + 8 * ARS;
            float* c = acc[mt][nt];
            *(uint32_t*)(dst + off0) = pk_half2(c[0], c[1]);
            *(uint32_t*)(dst + off1) = pk_half2(c[2], c[3]);
        }
    }
}

// ---------------- K_pre: merged weight-split (72 blocks) + inverse map (rest) ----------------
__global__ void k_pre(const float* __restrict__ Wd1, const float* __restrict__ Wd2,
                      const float* __restrict__ Wp1, const float* __restrict__ Wp2,
                      const float* __restrict__ Wu1, const float* __restrict__ Wu2,
                      const float* __restrict__ Wu3, const float* __restrict__ Wu4,
                      const float* __restrict__ bd1, const float* __restrict__ bd2,
                      const float* __restrict__ bp1, const float* __restrict__ bp2,
                      const float* __restrict__ bu1, const float* __restrict__ bu2,
                      const float* __restrict__ bu3, const float* __restrict__ bu4,
                      const float* __restrict__ ad,  const float* __restrict__ ap_,
                      const float* __restrict__ au1, const float* __restrict__ au2,
                      const int* __restrict__ sel, int M) {
    int b = blockIdx.x;
    if (b >= 72) {   // inverse-map blocks
        int m = (b - 72) * 256 + threadIdx.x;
        if (m < M) g_inv[sel[m]] = m;
        return;
    }
    int j = b >> 2;
    int slot = (j == 0) ? 0 : (j == 1) ? 1 : (j == 2) ? 2 :
               (j == 7) ? 3 : (j == 8) ? 4 : (j == 9) ? 5 : -1;
    {
        int t0 = (b & 3) * 1024;
#pragma unroll
        for (int it = 0; it < 4; it++) {
            int t = t0 + it * 256 + threadIdx.x;
            int n = t >> 6, k = t & 63;
            float v;
            if (j == 0)      v = Wd1[k * 64 + n];
            else if (j == 1) v = Wd2[k * 64 + n];
            else if (j == 2) v = Wp1[k * 64 + n];
            else if (j <= 6) { int ng = (j - 3) * 64 + n; v = (ng < 255) ? Wp2[k * 255 + ng] : 0.f; }
            else if (j == 7) v = Wu1[k * 64 + n];
            else if (j == 8) v = Wu2[k * 64 + n];
            else if (j == 9) v = Wu3[k * 64 + n];
            else             v = Wu4[(size_t)k * 512 + (j - 10) * 64 + n];
            if (slot >= 0) {
                __half h = __float2half(v);
                __half l = __float2half(v - __half2float(h));
                g_wh[slot * 4096 + t] = h;
                g_wl[slot * 4096 + t] = l;
            } else {
                int ch = (j <= 6) ? (j - 3) : (4 + j - 10);
                g_wx[ch * 4096 + n * 64 + k] = __float2half(v);
            }
        }
    }
    if ((b & 3) == 0 && threadIdx.x < 64) {
        int c = threadIdx.x; float bv = 0.f, a = 0.f;
        switch (j) {
            case 0: bv = bd1[c]; a = ad[c]; break;
            case 1: bv = bd2[c]; break;
            case 2: bv = bp1[c]; a = ap_[c]; break;
            case 3: case 4: case 5: case 6: {
                int ng = (j - 3) * 64 + c; bv = (ng < 255) ? bp2[ng] : 0.f; break; }
            case 7: bv = bu1[c]; a = au1[c]; break;
            case 8: bv = bu2[c]; a = au2[c]; break;
            case 9: bv = bu3[c]; break;
            default: bv = bu4[(j - 10) * 64 + c]; break;
        }
        g_bb[j * 64 + c] = bv;
        g_aw[j * 64 + c] = a;
    }
}

// ---------------- fused main kernel ----------------
__global__ __launch_bounds__(NTHR, 2)
void k_main(const float* __restrict__ X, const int* __restrict__ bin,
            const float* __restrict__ Wu1,
            float* __restrict__ pred, float* __restrict__ oct, float* __restrict__ newF) {
    extern __shared__ char smem[];
    const uint32_t sb = smem_u32(smem);
    int tid = threadIdx.x;
    int wid = tid >> 5, lane = tid & 31;
    int g = lane >> 2, tg = lane & 3;
    int mrow = (wid >> 1) * 32;
    int ncol = (wid & 1) * 32;
    int base = blockIdx.x * TILEM;

    float* wtail = (float*)(smem + SM_WTAIL);
    int*   smask = (int*)(smem + SM_MASK);

    // ---- prologue: X -> R0 fp16, mask/oct, wtail ----
    {
        const float4* Xr = (const float4*)(X + (size_t)base * 64);
#pragma unroll
        for (int it = 0; it < 8; it++) {
            int idx = it * NTHR + tid;
            int row = idx >> 4, q = idx & 15;
            float4 v = Xr[idx];
            *(uint2*)(smem + SM_R0 + row * ARS + q * 8) =
                make_uint2(pk_half2(v.x, v.y), pk_half2(v.z, v.w));
        }
        if (tid < TILEM) {
            const int* bp = bin + (size_t)(base + tid) * 8;
            int4 b0 = *(const int4*)bp;
            int4 b1 = *(const int4*)(bp + 4);
            int m = (b0.x != 0) | ((b0.y != 0) << 1) | ((b0.z != 0) << 2) | ((b0.w != 0) << 3)
                  | ((b1.x != 0) << 4) | ((b1.y != 0) << 5) | ((b1.z != 0) << 6) | ((b1.w != 0) << 7);
            smask[tid] = m;
            oct[base + tid] = (float)(m - 1);
        }
#pragma unroll
        for (int it = 0; it < 2; it++)
            wtail[it * NTHR + tid] = Wu1[4096 + it * NTHR + tid];
    }

    uint4 wr0, wr1, wr2, wr3;
    auto prefetchW = [&](int slot) {
        const uint4* sh = (const uint4*)(g_wh + slot * 4096);
        const uint4* sl = (const uint4*)(g_wl + slot * 4096);
        wr0 = sh[tid]; wr1 = sh[tid + 256];
        wr2 = sl[tid]; wr3 = sl[tid + 256];
    };
    auto commitW = [&](int buf) {   // hi at base, lo at base+9216
        char* b = smem + SM_W + buf * 18432;
        int i0 = tid, i1 = tid + 256;
        *(uint4*)(b + (i0 >> 3) * ARS + (i0 & 7) * 16)        = wr0;
        *(uint4*)(b + (i1 >> 3) * ARS + (i1 & 7) * 16)        = wr1;
        *(uint4*)(b + 9216 + (i0 >> 3) * ARS + (i0 & 7) * 16) = wr2;
        *(uint4*)(b + 9216 + (i1 >> 3) * ARS + (i1 & 7) * 16) = wr3;
    };

    uint32_t aoff = (uint32_t)((mrow + (lane & 7) + ((lane >> 3) & 1) * 8) * ARS
                              + ((lane >> 4) & 1) * 16);
    uint32_t woff = (uint32_t)((ncol + (lane & 7) + ((lane >> 4) & 1) * 8) * ARS
                              + ((lane >> 3) & 1) * 16);

    float acc[2][4][4];

    prefetchW(0);
    commitW(0);
    __syncthreads();          // prologue + W0 visible
    prefetchW(1);

    // ---- j0: h = prelu(X@Wd1+b) -> R1 fp16 ----
    zero_acc(acc);
    chain_gemm(sb + SM_R0 + aoff, sb + SM_W + woff, sb + SM_W + 9216 + woff, acc);
    add_bias(acc, 0, ncol, tg);
    apply_prelu(acc, 0, ncol, tg);
    store_f16(smem + SM_R1, acc, mrow, g, ncol, tg);
    __syncthreads();
    commitW(1);               // W_j1
    __syncthreads();
    prefetchW(2);

    // ---- j1: rec = X + h@Wd2 + b -> R0 ----
    zero_acc(acc);
    chain_gemm(sb + SM_R1 + aoff, sb + SM_W + 18432 + woff, sb + SM_W + 27648 + woff, acc);
    add_bias(acc, 1, ncol, tg);
    add_residual(smem + SM_R0, acc, mrow, g, ncol, tg);
    store_f16(smem + SM_R0, acc, mrow, g, ncol, tg);
    __syncthreads();
    commitW(0);               // W_j2
    __syncthreads();

    // ---- j2: p = prelu(rec@Wp1+b) -> R1 ----
    zero_acc(acc);
    chain_gemm(sb + SM_R0 + aoff, sb + SM_W + woff, sb + SM_W + 9216 + woff, acc);
    add_bias(acc, 2, ncol, tg);
    apply_prelu(acc, 2, ncol, tg);
    store_f16(smem + SM_R1, acc, mrow, g, ncol, tg);
    __syncthreads();

    // ---- stage pred W (4 chunks into full W region) + prefetch Wu1 ----
    {
        const uint4* src = (const uint4*)g_wx;
#pragma unroll
        for (int it = 0; it < 8; it++) {
            int i = it * NTHR + tid;            // 0..2047 uint4
            int c = i >> 9, w = i & 511;
            *(uint4*)(smem + SM_W + c * 9216 + (w >> 3) * ARS + (w & 7) * 16) = src[i];
        }
    }
    prefetchW(3);
    __syncthreads();

    // ---- pred group: 4 sync-free chunks (A = p in R1) ----
#pragma unroll
    for (int c = 0; c < 4; c++) {
        zero_acc(acc);
        heavy_gemm(sb + SM_R1 + aoff, sb + SM_W + c * 9216 + woff, acc);
        add_bias(acc, 3 + c, ncol, tg);
        int o0 = c * 64;
#pragma unroll
        for (int mt = 0; mt < 2; mt++) {
            int r = base + mrow + mt * 16 + g;
#pragma unroll
            for (int nt = 0; nt < 4; nt++) {
                int col = o0 + ncol + nt * 8 + tg * 2;
                float* cc = acc[mt][nt];
                float* p0 = pred + (size_t)r * 255 + col;
                float* p1 = pred + (size_t)(r + 8) * 255 + col;
                if (col < 255) { p0[0] = cc[0]; p1[0] = cc[2]; }
                if (col + 1 < 255) { p0[1] = cc[1]; p1[1] = cc[3]; }
            }
        }
    }
    __syncthreads();
    commitW(0);               // W_j7
    __syncthreads();
    prefetchW(4);

    // ---- j7: u1 = prelu([rec,bin]@Wu1+b) -> R1 ----
    zero_acc(acc);
    chain_gemm(sb + SM_R0 + aoff, sb + SM_W + woff, sb + SM_W + 9216 + woff, acc);
    add_bias(acc, 7, ncol, tg);
    {   // bin-concat tail (exact fp32)
#pragma unroll
        for (int mt = 0; mt < 2; mt++) {
            int rA = mrow + mt * 16 + g;
            int mA = smask[rA], mB = smask[rA + 8];
#pragma unroll
            for (int jj = 0; jj < 8; jj++) {
                bool bA = (mA >> jj) & 1, bB = (mB >> jj) & 1;
                if (bA | bB) {
#pragma unroll
                    for (int nt = 0; nt < 4; nt++) {
                        float2 t = *(const float2*)(wtail + jj * 64 + ncol + nt * 8 + tg * 2);
                        float* c = acc[mt][nt];
                        if (bA) { c[0] += 256.f * t.x; c[1] += 256.f * t.y; }
                        if (bB) { c[2] += 256.f * t.x; c[3] += 256.f * t.y; }
                    }
                }
            }
        }
    }
    apply_prelu(acc, 7, ncol, tg);
    store_f16(smem + SM_R1, acc, mrow, g, ncol, tg);
    __syncthreads();
    commitW(1);               // W_j8
    __syncthreads();
    prefetchW(5);

    // ---- j8: h2 = prelu(u1@Wu2+b) -> R0 (rec dead) ----
    zero_acc(acc);
    chain_gemm(sb + SM_R1 + aoff, sb + SM_W + 18432 + woff, sb + SM_W + 27648 + woff, acc);
    add_bias(acc, 8, ncol, tg);
    apply_prelu(acc, 8, ncol, tg);
    store_f16(smem + SM_R0, acc, mrow, g, ncol, tg);
    __syncthreads();
    commitW(0);               // W_j9
    __syncthreads();

    // ---- j9: u = u1 + h2@Wu3 + b -> R1 ----
    zero_acc(acc);
    chain_gemm(sb + SM_R0 + aoff, sb + SM_W + woff, sb + SM_W + 9216 + woff, acc);
    add_bias(acc, 9, ncol, tg);
    add_residual(smem + SM_R1, acc, mrow, g, ncol, tg);
    store_f16(smem + SM_R1, acc, mrow, g, ncol, tg);
    __syncthreads();

    // ---- stage up4 chunks 0-5 (0-3 -> W region, 4-5 -> R0) ----
    {
        const uint4* src = (const uint4*)(g_wx + 4 * 4096);
#pragma unroll
        for (int it = 0; it < 12; it++) {
            int i = it * NTHR + tid;            // 0..3071 uint4 (6 chunks)
            int c = i >> 9, w = i & 511;
            uint32_t dst = (c < 4) ? (uint32_t)(SM_W + c * 9216)
                                   : (uint32_t)(SM_R0 + (c - 4) * 9216);
            *(uint4*)(smem + dst + (w >> 3) * ARS + (w & 7) * 16) = src[i];
        }
    }
    __syncthreads();

    // ---- up4 chunks 0-5 (sync-free), then restage 6-7 ----
    auto up4_chunk = [&](int c, uint32_t wb) {
        zero_acc(acc);
        heavy_gemm(sb + SM_R1 + aoff, wb + woff, acc);
        add_bias(acc, 10 + c, ncol, tg);
#pragma unroll
        for (int mt = 0; mt < 2; mt++) {
            int rA = mrow + mt * 16 + g;
            bool okA = (smask[rA] >> c) & 1, okB = (smask[rA + 8] >> c) & 1;
            int iA = okA ? __ldg(&g_inv[(size_t)(base + rA) * 8 + c]) : 0;
            int iB = okB ? __ldg(&g_inv[(size_t)(base + rA + 8) * 8 + c]) : 0;
#pragma unroll
            for (int nt = 0; nt < 4; nt++) {
                int col = ncol + nt * 8 + tg * 2;
                float* cc = acc[mt][nt];
                if (okA) *(float2*)(newF + (size_t)iA * 64 + col) = make_float2(cc[0], cc[1]);
                if (okB) *(float2*)(newF + (size_t)iB * 64 + col) = make_float2(cc[2], cc[3]);
            }
        }
    };
#pragma unroll
    for (int c = 0; c < 4; c++) up4_chunk(c, sb + SM_W + c * 9216);
    up4_chunk(4, sb + SM_R0);
    up4_chunk(5, sb + SM_R0 + 9216);
    __syncthreads();
    {
        const uint4* src = (const uint4*)(g_wx + 10 * 4096);   // chunks 6,7
#pragma unroll
        for (int it = 0; it < 4; it++) {
            int i = it * NTHR + tid;            // 0..1023 uint4
            int c = i >> 9, w = i & 511;
            *(uint4*)(smem + SM_W + c * 9216 + (w >> 3) * ARS + (w & 7) * 16) = src[i];
        }
    }
    __syncthreads();
    up4_chunk(6, sb + SM_W);
    up4_chunk(7, sb + SM_W + 9216);
}

extern "C" void kernel_launch(void* const* d_in, const int* in_sizes, int n_in,
                              void* d_out, int out_size) {
    const float* X   = (const float*)d_in[0];
    const int*   bin = (const int*)d_in[1];
    const int*   sel = (const int*)d_in[2];
    const float* Wd1 = (const float*)d_in[3];
    const float* bd1 = (const float*)d_in[4];
    const float* ad  = (const float*)d_in[5];
    const float* Wd2 = (const float*)d_in[6];
    const float* bd2 = (const float*)d_in[7];
    const float* Wp1 = (const float*)d_in[8];
    const float* bp1 = (const float*)d_in[9];
    const float* ap  = (const float*)d_in[10];
    const float* Wp2 = (const float*)d_in[11];
    const float* bp2 = (const float*)d_in[12];
    const float* Wu1 = (const float*)d_in[13];
    const float* bu1 = (const float*)d_in[14];
    const float* au1 = (const float*)d_in[15];
    const float* Wu2 = (const float*)d_in[16];
    const float* bu2 = (const float*)d_in[17];
    const float* au2 = (const float*)d_in[18];
    const float* Wu3 = (const float*)d_in[19];
    const float* bu3 = (const float*)d_in[20];
    const float* Wu4 = (const float*)d_in[21];
    const float* bu4 = (const float*)d_in[22];

    int n = in_sizes[0] / 64;
    int M = in_sizes[2];
    float* newF = (float*)d_out;
    float* pred = newF + (size_t)M * 64;
    float* oct  = pred + (size_t)n * 255;

    cudaFuncSetAttribute(k_main, cudaFuncAttributeMaxDynamicSharedMemorySize, SM_TOTAL);

    int inv_blocks = (M + 255) / 256;
    k_pre<<<72 + inv_blocks, 256>>>(Wd1, Wd2, Wp1, Wp2, Wu1, Wu2, Wu3, Wu4,
                                    bd1, bd2, bp1, bp2, bu1, bu2, bu3, bu4,
                                    ad, ap, au1, au2, sel, M);
    k_main<<<n / TILEM, NTHR, SM_TOTAL>>>(X, bin, Wu1, pred, oct, newF);
}

// round 13
// speedup vs baseline: 1.2179x; 1.0482x over previous
#include <cuda_runtime.h>
#include <cuda_bf16.h>
#include <cuda_fp16.h>
#include <cstdint>

#define TILEM 128
#define NTHR  256
#define ARS   144      // smem row stride (bytes)

// smem byte offsets
#define SM_R0    0
#define SM_R1    18432
#define SM_W     36864   // chain bufA@0, bufB@18432 (hi+lo 9216 each); heavy chunks c*9216
#define SM_WTAIL 73728
#define SM_MASK  75776
#define SM_TOTAL 76288

// chain weights (fp16 hi/lo 2-term, [n][k] 64x64), slots: 0=Wd1 1=Wd2 2=Wp1 3=Wu1 4=Wu2 5=Wu3
__device__ __align__(16) __half g_wh[6 * 4096];
__device__ __align__(16) __half g_wl[6 * 4096];
// heavy weights (fp16 single, [n][k] 64x64), chunks: 0-3 = Wp2, 4-11 = Wu4
__device__ __align__(16) __half g_wx[12 * 4096];
__device__ __align__(16) float g_bb[18 * 64];
__device__ __align__(16) float g_aw[18 * 64];
__device__ int g_inv[(size_t)262144 * 8];

static __device__ __forceinline__ uint32_t smem_u32(const void* p) {
    uint32_t a;
    asm("{ .reg .u64 t; cvta.to.shared.u64 t, %1; cvt.u32.u64 %0, t; }" : "=r"(a) : "l"(p));
    return a;
}
static __device__ __forceinline__ uint32_t pk_half2(float a, float b) {
    __half2 t = __floats2half2_rn(a, b);
    return *(uint32_t*)&t;
}
static __device__ __forceinline__ float2 upk_half2(uint32_t u) {
    return __half22float2(*(__half2*)&u);
}
static __device__ __forceinline__ void mma_f16(float* c, const uint32_t* a, const uint32_t* b) {
    asm volatile(
        "mma.sync.aligned.m16n8k16.row.col.f32.f16.f16.f32 "
        "{%0,%1,%2,%3}, {%4,%5,%6,%7}, {%8,%9}, {%0,%1,%2,%3};"
        : "+f"(c[0]), "+f"(c[1]), "+f"(c[2]), "+f"(c[3])
        : "r"(a[0]), "r"(a[1]), "r"(a[2]), "r"(a[3]), "r"(b[0]), "r"(b[1]));
}
static __device__ __forceinline__ void ldm4(uint32_t* r, uint32_t addr) {
    asm volatile("ldmatrix.sync.aligned.m8n8.x4.shared.b16 {%0,%1,%2,%3}, [%4];"
        : "=r"(r[0]), "=r"(r[1]), "=r"(r[2]), "=r"(r[3]) : "r"(addr));
}
static __device__ __forceinline__ void zero_acc(float acc[2][4][4]) {
#pragma unroll
    for (int mt = 0; mt < 2; mt++)
#pragma unroll
        for (int nt = 0; nt < 4; nt++)
#pragma unroll
            for (int i = 0; i < 4; i++) acc[mt][nt][i] = 0.f;
}

// chain GEMM: A single fp16, W 2-term fp16 (Wh+Wl); warp tile m32 x n32
static __device__ __forceinline__ void chain_gemm(uint32_t aB, uint32_t wHb, uint32_t wLb,
                                                  float acc[2][4][4]) {
#pragma unroll
    for (int kc = 0; kc < 4; kc++) {
        uint32_t ko = kc * 32;
        uint32_t a2[2][4], bh[2][4], bl[2][4];
        ldm4(a2[0], aB + ko); ldm4(a2[1], aB + ko + 16 * ARS);
        ldm4(bh[0], wHb + ko); ldm4(bh[1], wHb + ko + 16 * ARS);
        ldm4(bl[0], wLb + ko); ldm4(bl[1], wLb + ko + 16 * ARS);
#pragma unroll
        for (int p2 = 0; p2 < 2; p2++)
#pragma unroll
            for (int h = 0; h < 2; h++) {
                int nt = p2 * 2 + h;
                const uint32_t* Bh = &bh[p2][h * 2];
                const uint32_t* Bl = &bl[p2][h * 2];
#pragma unroll
                for (int mt = 0; mt < 2; mt++) {
                    mma_f16(acc[mt][nt], a2[mt], Bh);
                    mma_f16(acc[mt][nt], a2[mt], Bl);
                }
            }
    }
}
// heavy GEMM: A cached in registers, W single fp16 from smem
static __device__ __forceinline__ void heavy_gemm(const uint32_t aC[4][2][4], uint32_t wb,
                                                  float acc[2][4][4]) {
#pragma unroll
    for (int kc = 0; kc < 4; kc++) {
        uint32_t ko = kc * 32;
        uint32_t bh[2][4];
        ldm4(bh[0], wb + ko); ldm4(bh[1], wb + ko + 16 * ARS);
#pragma unroll
        for (int p2 = 0; p2 < 2; p2++)
#pragma unroll
            for (int h = 0; h < 2; h++) {
                int nt = p2 * 2 + h;
                const uint32_t* Bh = &bh[p2][h * 2];
#pragma unroll
                for (int mt = 0; mt < 2; mt++)
                    mma_f16(acc[mt][nt], aC[kc][mt], Bh);
            }
    }
}

static __device__ __forceinline__ void add_bias(float acc[2][4][4], int j, int ncol, int tg) {
    const float* bb = g_bb + j * 64;
#pragma unroll
    for (int nt = 0; nt < 4; nt++) {
        float2 bv = __ldg((const float2*)(bb + ncol + nt * 8 + tg * 2));
#pragma unroll
        for (int mt = 0; mt < 2; mt++) {
            float* c = acc[mt][nt];
            c[0] += bv.x; c[1] += bv.y; c[2] += bv.x; c[3] += bv.y;
        }
    }
}
static __device__ __forceinline__ void apply_prelu(float acc[2][4][4], int j, int ncol, int tg) {
    const float* aw = g_aw + j * 64;
#pragma unroll
    for (int nt = 0; nt < 4; nt++) {
        float2 av = __ldg((const float2*)(aw + ncol + nt * 8 + tg * 2));
#pragma unroll
        for (int mt = 0; mt < 2; mt++) {
            float* c = acc[mt][nt];
            c[0] = c[0] >= 0.f ? c[0] : av.x * c[0];
            c[1] = c[1] >= 0.f ? c[1] : av.y * c[1];
            c[2] = c[2] >= 0.f ? c[2] : av.x * c[2];
            c[3] = c[3] >= 0.f ? c[3] : av.y * c[3];
        }
    }
}
static __device__ __forceinline__ void add_residual(const char* rgn, float acc[2][4][4],
                                                    int mrow, int g, int ncol, int tg) {
#pragma unroll
    for (int mt = 0; mt < 2; mt++) {
        int r = mrow + mt * 16 + g;
#pragma unroll
        for (int nt = 0; nt < 4; nt++) {
            uint32_t off0 = r * ARS + (ncol + nt * 8 + tg * 2) * 2;
            uint32_t off1 = off0 + 8 * ARS;
            float2 v0 = upk_half2(*(const uint32_t*)(rgn + off0));
            float2 v1 = upk_half2(*(const uint32_t*)(rgn + off1));
            float* c = acc[mt][nt];
            c[0] += v0.x; c[1] += v0.y; c[2] += v1.x; c[3] += v1.y;
        }
    }
}
static __device__ __forceinline__ void store_f16(char* dst, float acc[2][4][4],
                                                 int mrow, int g, int ncol, int tg) {
#pragma unroll
    for (int mt = 0; mt < 2; mt++) {
        int r = mrow + mt * 16 + g;
#pragma unroll
        for (int nt = 0; nt < 4; nt++) {
            uint32_t off0 = r * ARS + (ncol + nt * 8 + tg * 2) * 2;
            uint32_t off1 = off0 + 8 * ARS;
            float* c = acc[mt][nt];
            *(uint32_t*)(dst + off0) = pk_half2(c[0], c[1]);
            *(uint32_t*)(dst + off1) = pk_half2(c[2], c[3]);
        }
    }
}

// ---------------- K_pre: merged weight-split (72 blocks) + inverse map (rest) ----------------
__global__ void k_pre(const float* __restrict__ Wd1, const float* __restrict__ Wd2,
                      const float* __restrict__ Wp1, const float* __restrict__ Wp2,
                      const float* __restrict__ Wu1, const float* __restrict__ Wu2,
                      const float* __restrict__ Wu3, const float* __restrict__ Wu4,
                      const float* __restrict__ bd1, const float* __restrict__ bd2,
                      const float* __restrict__ bp1, const float* __restrict__ bp2,
                      const float* __restrict__ bu1, const float* __restrict__ bu2,
                      const float* __restrict__ bu3, const float* __restrict__ bu4,
                      const float* __restrict__ ad,  const float* __restrict__ ap_,
                      const float* __restrict__ au1, const float* __restrict__ au2,
                      const int* __restrict__ sel, int M) {
    int b = blockIdx.x;
    if (b >= 72) {   // inverse-map blocks
        int m = (b - 72) * 256 + threadIdx.x;
        if (m < M) g_inv[sel[m]] = m;
        return;
    }
    int j = b >> 2;
    int slot = (j == 0) ? 0 : (j == 1) ? 1 : (j == 2) ? 2 :
               (j == 7) ? 3 : (j == 8) ? 4 : (j == 9) ? 5 : -1;
    {
        int t0 = (b & 3) * 1024;
#pragma unroll
        for (int it = 0; it < 4; it++) {
            int t = t0 + it * 256 + threadIdx.x;
            int n = t >> 6, k = t & 63;
            float v;
            if (j == 0)      v = Wd1[k * 64 + n];
            else if (j == 1) v = Wd2[k * 64 + n];
            else if (j == 2) v = Wp1[k * 64 + n];
            else if (j <= 6) { int ng = (j - 3) * 64 + n; v = (ng < 255) ? Wp2[k * 255 + ng] : 0.f; }
            else if (j == 7) v = Wu1[k * 64 + n];
            else if (j == 8) v = Wu2[k * 64 + n];
            else if (j == 9) v = Wu3[k * 64 + n];
            else             v = Wu4[(size_t)k * 512 + (j - 10) * 64 + n];
            if (slot >= 0) {
                __half h = __float2half(v);
                __half l = __float2half(v - __half2float(h));
                g_wh[slot * 4096 + t] = h;
                g_wl[slot * 4096 + t] = l;
            } else {
                int ch = (j <= 6) ? (j - 3) : (4 + j - 10);
                g_wx[ch * 4096 + n * 64 + k] = __float2half(v);
            }
        }
    }
    if ((b & 3) == 0 && threadIdx.x < 64) {
        int c = threadIdx.x; float bv = 0.f, a = 0.f;
        switch (j) {
            case 0: bv = bd1[c]; a = ad[c]; break;
            case 1: bv = bd2[c]; break;
            case 2: bv = bp1[c]; a = ap_[c]; break;
            case 3: case 4: case 5: case 6: {
                int ng = (j - 3) * 64 + c; bv = (ng < 255) ? bp2[ng] : 0.f; break; }
            case 7: bv = bu1[c]; a = au1[c]; break;
            case 8: bv = bu2[c]; a = au2[c]; break;
            case 9: bv = bu3[c]; break;
            default: bv = bu4[(j - 10) * 64 + c]; break;
        }
        g_bb[j * 64 + c] = bv;
        g_aw[j * 64 + c] = a;
    }
}

// ---------------- fused main kernel ----------------
__global__ __launch_bounds__(NTHR, 2)
void k_main(const float* __restrict__ X, const int* __restrict__ bin,
            const float* __restrict__ Wu1,
            float* __restrict__ pred, float* __restrict__ oct, float* __restrict__ newF) {
    extern __shared__ char smem[];
    const uint32_t sb = smem_u32(smem);
    int tid = threadIdx.x;
    int wid = tid >> 5, lane = tid & 31;
    int g = lane >> 2, tg = lane & 3;
    int mrow = (wid >> 1) * 32;
    int ncol = (wid & 1) * 32;
    int base = blockIdx.x * TILEM;

    float* wtail = (float*)(smem + SM_WTAIL);
    int*   smask = (int*)(smem + SM_MASK);

    // ---- prologue: X -> R0 fp16, mask/oct, wtail ----
    {
        const float4* Xr = (const float4*)(X + (size_t)base * 64);
#pragma unroll
        for (int it = 0; it < 8; it++) {
            int idx = it * NTHR + tid;
            int row = idx >> 4, q = idx & 15;
            float4 v = Xr[idx];
            *(uint2*)(smem + SM_R0 + row * ARS + q * 8) =
                make_uint2(pk_half2(v.x, v.y), pk_half2(v.z, v.w));
        }
        if (tid < TILEM) {
            const int* bp = bin + (size_t)(base + tid) * 8;
            int4 b0 = *(const int4*)bp;
            int4 b1 = *(const int4*)(bp + 4);
            int m = (b0.x != 0) | ((b0.y != 0) << 1) | ((b0.z != 0) << 2) | ((b0.w != 0) << 3)
                  | ((b1.x != 0) << 4) | ((b1.y != 0) << 5) | ((b1.z != 0) << 6) | ((b1.w != 0) << 7);
            smask[tid] = m;
            oct[base + tid] = (float)(m - 1);
        }
#pragma unroll
        for (int it = 0; it < 2; it++)
            wtail[it * NTHR + tid] = Wu1[4096 + it * NTHR + tid];
    }

    uint4 wr0, wr1, wr2, wr3;
    auto prefetchW = [&](int slot) {
        const uint4* sh = (const uint4*)(g_wh + slot * 4096);
        const uint4* sl = (const uint4*)(g_wl + slot * 4096);
        wr0 = sh[tid]; wr1 = sh[tid + 256];
        wr2 = sl[tid]; wr3 = sl[tid + 256];
    };
    auto commitW = [&](int buf) {   // hi at base, lo at base+9216
        char* b = smem + SM_W + buf * 18432;
        int i0 = tid, i1 = tid + 256;
        *(uint4*)(b + (i0 >> 3) * ARS + (i0 & 7) * 16)        = wr0;
        *(uint4*)(b + (i1 >> 3) * ARS + (i1 & 7) * 16)        = wr1;
        *(uint4*)(b + 9216 + (i0 >> 3) * ARS + (i0 & 7) * 16) = wr2;
        *(uint4*)(b + 9216 + (i1 >> 3) * ARS + (i1 & 7) * 16) = wr3;
    };

    uint32_t aoff = (uint32_t)((mrow + (lane & 7) + ((lane >> 3) & 1) * 8) * ARS
                              + ((lane >> 4) & 1) * 16);
    uint32_t woff = (uint32_t)((ncol + (lane & 7) + ((lane >> 4) & 1) * 8) * ARS
                              + ((lane >> 3) & 1) * 16);

    float acc[2][4][4];

    prefetchW(0);
    commitW(0);
    __syncthreads();          // prologue + W0 visible
    prefetchW(1);

    // ---- j0: h = prelu(X@Wd1+b) -> R1 fp16 ----
    zero_acc(acc);
    chain_gemm(sb + SM_R0 + aoff, sb + SM_W + woff, sb + SM_W + 9216 + woff, acc);
    add_bias(acc, 0, ncol, tg);
    apply_prelu(acc, 0, ncol, tg);
    store_f16(smem + SM_R1, acc, mrow, g, ncol, tg);
    __syncthreads();
    commitW(1);               // W_j1
    __syncthreads();
    prefetchW(2);

    // ---- j1: rec = X + h@Wd2 + b -> R0 ----
    zero_acc(acc);
    chain_gemm(sb + SM_R1 + aoff, sb + SM_W + 18432 + woff, sb + SM_W + 27648 + woff, acc);
    add_bias(acc, 1, ncol, tg);
    add_residual(smem + SM_R0, acc, mrow, g, ncol, tg);
    store_f16(smem + SM_R0, acc, mrow, g, ncol, tg);
    __syncthreads();
    commitW(0);               // W_j2
    __syncthreads();

    // ---- j2: p = prelu(rec@Wp1+b) -> R1 ----
    zero_acc(acc);
    chain_gemm(sb + SM_R0 + aoff, sb + SM_W + woff, sb + SM_W + 9216 + woff, acc);
    add_bias(acc, 2, ncol, tg);
    apply_prelu(acc, 2, ncol, tg);
    store_f16(smem + SM_R1, acc, mrow, g, ncol, tg);
    __syncthreads();

    // ---- stage pred W (4 chunks into full W region) + prefetch Wu1 ----
    {
        const uint4* src = (const uint4*)g_wx;
#pragma unroll
        for (int it = 0; it < 8; it++) {
            int i = it * NTHR + tid;            // 0..2047 uint4
            int c = i >> 9, w = i & 511;
            *(uint4*)(smem + SM_W + c * 9216 + (w >> 3) * ARS + (w & 7) * 16) = src[i];
        }
    }
    prefetchW(3);
    __syncthreads();

    // ---- pred group: A = p cached in registers; 4 sync-free chunks ----
    {
        uint32_t aC[4][2][4];
        uint32_t aR1 = sb + SM_R1 + aoff;
#pragma unroll
        for (int kc = 0; kc < 4; kc++) {
            ldm4(aC[kc][0], aR1 + kc * 32);
            ldm4(aC[kc][1], aR1 + kc * 32 + 16 * ARS);
        }
#pragma unroll
        for (int c = 0; c < 4; c++) {
            zero_acc(acc);
            heavy_gemm(aC, sb + SM_W + c * 9216 + woff, acc);
            add_bias(acc, 3 + c, ncol, tg);
            int o0 = c * 64;
#pragma unroll
            for (int mt = 0; mt < 2; mt++) {
                int r = base + mrow + mt * 16 + g;
#pragma unroll
                for (int nt = 0; nt < 4; nt++) {
                    int col = o0 + ncol + nt * 8 + tg * 2;
                    float* cc = acc[mt][nt];
                    float* p0 = pred + (size_t)r * 255 + col;
                    float* p1 = pred + (size_t)(r + 8) * 255 + col;
                    if (col < 255) { p0[0] = cc[0]; p1[0] = cc[2]; }
                    if (col + 1 < 255) { p0[1] = cc[1]; p1[1] = cc[3]; }
                }
            }
        }
    }
    __syncthreads();
    commitW(0);               // W_j7
    __syncthreads();
    prefetchW(4);

    // ---- j7: u1 = prelu([rec,bin]@Wu1+b) -> R1 ----
    zero_acc(acc);
    chain_gemm(sb + SM_R0 + aoff, sb + SM_W + woff, sb + SM_W + 9216 + woff, acc);
    add_bias(acc, 7, ncol, tg);
    {   // bin-concat tail (exact fp32)
#pragma unroll
        for (int mt = 0; mt < 2; mt++) {
            int rA = mrow + mt * 16 + g;
            int mA = smask[rA], mB = smask[rA + 8];
#pragma unroll
            for (int jj = 0; jj < 8; jj++) {
                bool bA = (mA >> jj) & 1, bB = (mB >> jj) & 1;
                if (bA | bB) {
#pragma unroll
                    for (int nt = 0; nt < 4; nt++) {
                        float2 t = *(const float2*)(wtail + jj * 64 + ncol + nt * 8 + tg * 2);
                        float* c = acc[mt][nt];
                        if (bA) { c[0] += 256.f * t.x; c[1] += 256.f * t.y; }
                        if (bB) { c[2] += 256.f * t.x; c[3] += 256.f * t.y; }
                    }
                }
            }
        }
    }
    apply_prelu(acc, 7, ncol, tg);
    store_f16(smem + SM_R1, acc, mrow, g, ncol, tg);
    __syncthreads();
    commitW(1);               // W_j8
    __syncthreads();
    prefetchW(5);

    // ---- j8: h2 = prelu(u1@Wu2+b) -> R0 (rec dead) ----
    zero_acc(acc);
    chain_gemm(sb + SM_R1 + aoff, sb + SM_W + 18432 + woff, sb + SM_W + 27648 + woff, acc);
    add_bias(acc, 8, ncol, tg);
    apply_prelu(acc, 8, ncol, tg);
    store_f16(smem + SM_R0, acc, mrow, g, ncol, tg);
    __syncthreads();
    commitW(0);               // W_j9
    __syncthreads();

    // ---- j9: u = u1 + h2@Wu3 + b -> R1 ----
    zero_acc(acc);
    chain_gemm(sb + SM_R0 + aoff, sb + SM_W + woff, sb + SM_W + 9216 + woff, acc);
    add_bias(acc, 9, ncol, tg);
    add_residual(smem + SM_R1, acc, mrow, g, ncol, tg);
    store_f16(smem + SM_R1, acc, mrow, g, ncol, tg);
    __syncthreads();

    // ---- stage up4 chunks 0-5 (0-3 -> W region, 4-5 -> R0) ----
    {
        const uint4* src = (const uint4*)(g_wx + 4 * 4096);
#pragma unroll
        for (int it = 0; it < 12; it++) {
            int i = it * NTHR + tid;            // 0..3071 uint4 (6 chunks)
            int c = i >> 9, w = i & 511;
            uint32_t dst = (c < 4) ? (uint32_t)(SM_W + c * 9216)
                                   : (uint32_t)(SM_R0 + (c - 4) * 9216);
            *(uint4*)(smem + dst + (w >> 3) * ARS + (w & 7) * 16) = src[i];
        }
    }
    __syncthreads();

    // ---- up4 group: A = u cached in registers (R1 untouched by staging) ----
    {
        uint32_t aC[4][2][4];
        uint32_t aR1 = sb + SM_R1 + aoff;
#pragma unroll
        for (int kc = 0; kc < 4; kc++) {
            ldm4(aC[kc][0], aR1 + kc * 32);
            ldm4(aC[kc][1], aR1 + kc * 32 + 16 * ARS);
        }
        auto up4_chunk = [&](int c, uint32_t wb) {
            zero_acc(acc);
            heavy_gemm(aC, wb + woff, acc);
            add_bias(acc, 10 + c, ncol, tg);
#pragma unroll
            for (int mt = 0; mt < 2; mt++) {
                int rA = mrow + mt * 16 + g;
                bool okA = (smask[rA] >> c) & 1, okB = (smask[rA + 8] >> c) & 1;
                int iA = okA ? __ldg(&g_inv[(size_t)(base + rA) * 8 + c]) : 0;
                int iB = okB ? __ldg(&g_inv[(size_t)(base + rA + 8) * 8 + c]) : 0;
#pragma unroll
                for (int nt = 0; nt < 4; nt++) {
                    int col = ncol + nt * 8 + tg * 2;
                    float* cc = acc[mt][nt];
                    if (okA) *(float2*)(newF + (size_t)iA * 64 + col) = make_float2(cc[0], cc[1]);
                    if (okB) *(float2*)(newF + (size_t)iB * 64 + col) = make_float2(cc[2], cc[3]);
                }
            }
        };
#pragma unroll
        for (int c = 0; c < 4; c++) up4_chunk(c, sb + SM_W + c * 9216);
        up4_chunk(4, sb + SM_R0);
        up4_chunk(5, sb + SM_R0 + 9216);
        __syncthreads();
        {
            const uint4* src = (const uint4*)(g_wx + 10 * 4096);   // chunks 6,7
#pragma unroll
            for (int it = 0; it < 4; it++) {
                int i = it * NTHR + tid;            // 0..1023 uint4
                int c = i >> 9, w = i & 511;
                *(uint4*)(smem + SM_W + c * 9216 + (w >> 3) * ARS + (w & 7) * 16) = src[i];
            }
        }
        __syncthreads();
        up4_chunk(6, sb + SM_W);
        up4_chunk(7, sb + SM_W + 9216);
    }
}

extern "C" void kernel_launch(void* const* d_in, const int* in_sizes, int n_in,
                              void* d_out, int out_size) {
    const float* X   = (const float*)d_in[0];
    const int*   bin = (const int*)d_in[1];
    const int*   sel = (const int*)d_in[2];
    const float* Wd1 = (const float*)d_in[3];
    const float* bd1 = (const float*)d_in[4];
    const float* ad  = (const float*)d_in[5];
    const float* Wd2 = (const float*)d_in[6];
    const float* bd2 = (const float*)d_in[7];
    const float* Wp1 = (const float*)d_in[8];
    const float* bp1 = (const float*)d_in[9];
    const float* ap  = (const float*)d_in[10];
    const float* Wp2 = (const float*)d_in[11];
    const float* bp2 = (const float*)d_in[12];
    const float* Wu1 = (const float*)d_in[13];
    const float* bu1 = (const float*)d_in[14];
    const float* au1 = (const float*)d_in[15];
    const float* Wu2 = (const float*)d_in[16];
    const float* bu2 = (const float*)d_in[17];
    const float* au2 = (const float*)d_in[18];
    const float* Wu3 = (const float*)d_in[19];
    const float* bu3 = (const float*)d_in[20];
    const float* Wu4 = (const float*)d_in[21];
    const float* bu4 = (const float*)d_in[22];

    int n = in_sizes[0] / 64;
    int M = in_sizes[2];
    float* newF = (float*)d_out;
    float* pred = newF + (size_t)M * 64;
    float* oct  = pred + (size_t)n * 255;

    cudaFuncSetAttribute(k_main, cudaFuncAttributeMaxDynamicSharedMemorySize, SM_TOTAL);

    int inv_blocks = (M + 255) / 256;
    k_pre<<<72 + inv_blocks, 256>>>(Wd1, Wd2, Wp1, Wp2, Wu1, Wu2, Wu3, Wu4,
                                    bd1, bd2, bp1, bp2, bu1, bu2, bu3, bu4,
                                    ad, ap, au1, au2, sel, M);
    k_main<<<n / TILEM, NTHR, SM_TOTAL>>>(X, bin, Wu1, pred, oct, newF);
}

// round 14
// speedup vs baseline: 1.2955x; 1.0637x over previous
#include <cuda_runtime.h>
#include <cuda_bf16.h>
#include <cuda_fp16.h>
#include <cstdint>

#define TILEM 128
#define NTHR  256
#define ARS   144      // smem row stride (bytes)

// smem byte offsets
#define SM_R0    0
#define SM_R1    18432
#define SM_W     36864   // chain W double buffer: bufA@0, bufB@18432 (hi+lo 9216 each)
#define SM_WX    73728   // heavy W region: 4 chunks x 9216
#define SM_WTAIL 110592
#define SM_MASK  112640
#define SM_TOTAL 113152

// chain weights (fp16 hi/lo 2-term, [n][k] 64x64), slots: 0=Wd1 1=Wd2 2=Wp1 3=Wu1 4=Wu2 5=Wu3
__device__ __align__(16) __half g_wh[6 * 4096];
__device__ __align__(16) __half g_wl[6 * 4096];
// heavy weights (fp16 single, [n][k] 64x64), chunks: 0-3 = Wp2, 4-11 = Wu4
__device__ __align__(16) __half g_wx[12 * 4096];
__device__ __align__(16) float g_bb[18 * 64];
__device__ __align__(16) float g_aw[18 * 64];
__device__ int g_inv[(size_t)262144 * 8];

static __device__ __forceinline__ uint32_t smem_u32(const void* p) {
    uint32_t a;
    asm("{ .reg .u64 t; cvta.to.shared.u64 t, %1; cvt.u32.u64 %0, t; }" : "=r"(a) : "l"(p));
    return a;
}
static __device__ __forceinline__ uint32_t pk_half2(float a, float b) {
    __half2 t = __floats2half2_rn(a, b);
    return *(uint32_t*)&t;
}
static __device__ __forceinline__ float2 upk_half2(uint32_t u) {
    return __half22float2(*(__half2*)&u);
}
static __device__ __forceinline__ void mma_f16(float* c, const uint32_t* a, const uint32_t* b) {
    asm volatile(
        "mma.sync.aligned.m16n8k16.row.col.f32.f16.f16.f32 "
        "{%0,%1,%2,%3}, {%4,%5,%6,%7}, {%8,%9}, {%0,%1,%2,%3};"
        : "+f"(c[0]), "+f"(c[1]), "+f"(c[2]), "+f"(c[3])
        : "r"(a[0]), "r"(a[1]), "r"(a[2]), "r"(a[3]), "r"(b[0]), "r"(b[1]));
}
static __device__ __forceinline__ void ldm4(uint32_t* r, uint32_t addr) {
    asm volatile("ldmatrix.sync.aligned.m8n8.x4.shared.b16 {%0,%1,%2,%3}, [%4];"
        : "=r"(r[0]), "=r"(r[1]), "=r"(r[2]), "=r"(r[3]) : "r"(addr));
}
static __device__ __forceinline__ void cpa16(uint32_t dst, const void* src) {
    asm volatile("cp.async.cg.shared.global [%0], [%1], 16;" :: "r"(dst), "l"(src));
}
#define CP_COMMIT() asm volatile("cp.async.commit_group;" ::: "memory")
#define CP_WAIT(n)  asm volatile("cp.async.wait_group %0;" :: "n"(n) : "memory")

static __device__ __forceinline__ void zero_acc(float acc[2][4][4]) {
#pragma unroll
    for (int mt = 0; mt < 2; mt++)
#pragma unroll
        for (int nt = 0; nt < 4; nt++)
#pragma unroll
            for (int i = 0; i < 4; i++) acc[mt][nt][i] = 0.f;
}

// chain GEMM: A single fp16, W 2-term fp16 (Wh+Wl); warp tile m32 x n32
static __device__ __forceinline__ void chain_gemm(uint32_t aB, uint32_t wHb, uint32_t wLb,
                                                  float acc[2][4][4]) {
#pragma unroll
    for (int kc = 0; kc < 4; kc++) {
        uint32_t ko = kc * 32;
        uint32_t a2[2][4], bh[2][4], bl[2][4];
        ldm4(a2[0], aB + ko); ldm4(a2[1], aB + ko + 16 * ARS);
        ldm4(bh[0], wHb + ko); ldm4(bh[1], wHb + ko + 16 * ARS);
        ldm4(bl[0], wLb + ko); ldm4(bl[1], wLb + ko + 16 * ARS);
#pragma unroll
        for (int p2 = 0; p2 < 2; p2++)
#pragma unroll
            for (int h = 0; h < 2; h++) {
                int nt = p2 * 2 + h;
                const uint32_t* Bh = &bh[p2][h * 2];
                const uint32_t* Bl = &bl[p2][h * 2];
#pragma unroll
                for (int mt = 0; mt < 2; mt++) {
                    mma_f16(acc[mt][nt], a2[mt], Bh);
                    mma_f16(acc[mt][nt], a2[mt], Bl);
                }
            }
    }
}
// heavy GEMM: A cached in registers, W single fp16 from smem
static __device__ __forceinline__ void heavy_gemm(const uint32_t aC[4][2][4], uint32_t wb,
                                                  float acc[2][4][4]) {
#pragma unroll
    for (int kc = 0; kc < 4; kc++) {
        uint32_t ko = kc * 32;
        uint32_t bh[2][4];
        ldm4(bh[0], wb + ko); ldm4(bh[1], wb + ko + 16 * ARS);
#pragma unroll
        for (int p2 = 0; p2 < 2; p2++)
#pragma unroll
            for (int h = 0; h < 2; h++) {
                int nt = p2 * 2 + h;
                const uint32_t* Bh = &bh[p2][h * 2];
#pragma unroll
                for (int mt = 0; mt < 2; mt++)
                    mma_f16(acc[mt][nt], aC[kc][mt], Bh);
            }
    }
}

static __device__ __forceinline__ void add_bias(float acc[2][4][4], int j, int ncol, int tg) {
    const float* bb = g_bb + j * 64;
#pragma unroll
    for (int nt = 0; nt < 4; nt++) {
        float2 bv = __ldg((const float2*)(bb + ncol + nt * 8 + tg * 2));
#pragma unroll
        for (int mt = 0; mt < 2; mt++) {
            float* c = acc[mt][nt];
            c[0] += bv.x; c[1] += bv.y; c[2] += bv.x; c[3] += bv.y;
        }
    }
}
static __device__ __forceinline__ void apply_prelu(float acc[2][4][4], int j, int ncol, int tg) {
    const float* aw = g_aw + j * 64;
#pragma unroll
    for (int nt = 0; nt < 4; nt++) {
        float2 av = __ldg((const float2*)(aw + ncol + nt * 8 + tg * 2));
#pragma unroll
        for (int mt = 0; mt < 2; mt++) {
            float* c = acc[mt][nt];
            c[0] = c[0] >= 0.f ? c[0] : av.x * c[0];
            c[1] = c[1] >= 0.f ? c[1] : av.y * c[1];
            c[2] = c[2] >= 0.f ? c[2] : av.x * c[2];
            c[3] = c[3] >= 0.f ? c[3] : av.y * c[3];
        }
    }
}
static __device__ __forceinline__ void add_residual(const char* rgn, float acc[2][4][4],
                                                    int mrow, int g, int ncol, int tg) {
#pragma unroll
    for (int mt = 0; mt < 2; mt++) {
        int r = mrow + mt * 16 + g;
#pragma unroll
        for (int nt = 0; nt < 4; nt++) {
            uint32_t off0 = r * ARS + (ncol + nt * 8 + tg * 2) * 2;
            uint32_t off1 = off0 + 8 * ARS;
            float2 v0 = upk_half2(*(const uint32_t*)(rgn + off0));
            float2 v1 = upk_half2(*(const uint32_t*)(rgn + off1));
            float* c = acc[mt][nt];
            c[0] += v0.x; c[1] += v0.y; c[2] += v1.x; c[3] += v1.y;
        }
    }
}
static __device__ __forceinline__ void store_f16(char* dst, float acc[2][4][4],
                                                 int mrow, int g, int ncol, int tg) {
#pragma unroll
    for (int mt = 0; mt < 2; mt++) {
        int r = mrow + mt * 16 + g;
#pragma unroll
        for (int nt = 0; nt < 4; nt++) {
            uint32_t off0 = r * ARS + (ncol + nt * 8 + tg * 2) * 2;
            uint32_t off1 = off0 + 8 * ARS;
            float* c = acc[mt][nt];
            *(uint32_t*)(dst + off0) = pk_half2(c[0], c[1]);
            *(uint32_t*)(dst + off1) = pk_half2(c[2], c[3]);
        }
    }
}

// ---------------- K_pre: merged weight-split (72 blocks) + inverse map (rest) ----------------
__global__ void k_pre(const float* __restrict__ Wd1, const float* __restrict__ Wd2,
                      const float* __restrict__ Wp1, const float* __restrict__ Wp2,
                      const float* __restrict__ Wu1, const float* __restrict__ Wu2,
                      const float* __restrict__ Wu3, const float* __restrict__ Wu4,
                      const float* __restrict__ bd1, const float* __restrict__ bd2,
                      const float* __restrict__ bp1, const float* __restrict__ bp2,
                      const float* __restrict__ bu1, const float* __restrict__ bu2,
                      const float* __restrict__ bu3, const float* __restrict__ bu4,
                      const float* __restrict__ ad,  const float* __restrict__ ap_,
                      const float* __restrict__ au1, const float* __restrict__ au2,
                      const int* __restrict__ sel, int M) {
    int b = blockIdx.x;
    if (b >= 72) {   // inverse-map blocks
        int m = (b - 72) * 256 + threadIdx.x;
        if (m < M) g_inv[sel[m]] = m;
        return;
    }
    int j = b >> 2;
    int slot = (j == 0) ? 0 : (j == 1) ? 1 : (j == 2) ? 2 :
               (j == 7) ? 3 : (j == 8) ? 4 : (j == 9) ? 5 : -1;
    {
        int t0 = (b & 3) * 1024;
#pragma unroll
        for (int it = 0; it < 4; it++) {
            int t = t0 + it * 256 + threadIdx.x;
            int n = t >> 6, k = t & 63;
            float v;
            if (j == 0)      v = Wd1[k * 64 + n];
            else if (j == 1) v = Wd2[k * 64 + n];
            else if (j == 2) v = Wp1[k * 64 + n];
            else if (j <= 6) { int ng = (j - 3) * 64 + n; v = (ng < 255) ? Wp2[k * 255 + ng] : 0.f; }
            else if (j == 7) v = Wu1[k * 64 + n];
            else if (j == 8) v = Wu2[k * 64 + n];
            else if (j == 9) v = Wu3[k * 64 + n];
            else             v = Wu4[(size_t)k * 512 + (j - 10) * 64 + n];
            if (slot >= 0) {
                __half h = __float2half(v);
                __half l = __float2half(v - __half2float(h));
                g_wh[slot * 4096 + t] = h;
                g_wl[slot * 4096 + t] = l;
            } else {
                int ch = (j <= 6) ? (j - 3) : (4 + j - 10);
                g_wx[ch * 4096 + n * 64 + k] = __float2half(v);
            }
        }
    }
    if ((b & 3) == 0 && threadIdx.x < 64) {
        int c = threadIdx.x; float bv = 0.f, a = 0.f;
        switch (j) {
            case 0: bv = bd1[c]; a = ad[c]; break;
            case 1: bv = bd2[c]; break;
            case 2: bv = bp1[c]; a = ap_[c]; break;
            case 3: case 4: case 5: case 6: {
                int ng = (j - 3) * 64 + c; bv = (ng < 255) ? bp2[ng] : 0.f; break; }
            case 7: bv = bu1[c]; a = au1[c]; break;
            case 8: bv = bu2[c]; a = au2[c]; break;
            case 9: bv = bu3[c]; break;
            default: bv = bu4[(j - 10) * 64 + c]; break;
        }
        g_bb[j * 64 + c] = bv;
        g_aw[j * 64 + c] = a;
    }
}

// ---------------- fused main kernel ----------------
__global__ __launch_bounds__(NTHR, 2)
void k_main(const float* __restrict__ X, const int* __restrict__ bin,
            const float* __restrict__ Wu1,
            float* __restrict__ pred, float* __restrict__ oct, float* __restrict__ newF) {
    extern __shared__ char smem[];
    const uint32_t sb = smem_u32(smem);
    int tid = threadIdx.x;
    int wid = tid >> 5, lane = tid & 31;
    int g = lane >> 2, tg = lane & 3;
    int mrow = (wid >> 1) * 32;
    int ncol = (wid & 1) * 32;
    int base = blockIdx.x * TILEM;

    float* wtail = (float*)(smem + SM_WTAIL);
    int*   smask = (int*)(smem + SM_MASK);

    // async-stage 4 heavy chunks from g_wx[ch0..] into smem region (2048 x 16B)
    auto stage4 = [&](uint32_t region, int ch0) {
#pragma unroll
        for (int it = 0; it < 8; it++) {
            int i = it * NTHR + tid;
            int c = i >> 9, w = i & 511;
            cpa16(sb + region + c * 9216 + (w >> 3) * ARS + (w & 7) * 16,
                  g_wx + (size_t)(ch0 + c) * 4096 + (size_t)w * 8);
        }
        CP_COMMIT();
    };

    // ---- issue pred W (chunks 0-3 -> SM_WX) immediately ----
    stage4(SM_WX, 0);

    // ---- prologue: X -> R0 fp16, mask/oct, wtail ----
    {
        const float4* Xr = (const float4*)(X + (size_t)base * 64);
#pragma unroll
        for (int it = 0; it < 8; it++) {
            int idx = it * NTHR + tid;
            int row = idx >> 4, q = idx & 15;
            float4 v = Xr[idx];
            *(uint2*)(smem + SM_R0 + row * ARS + q * 8) =
                make_uint2(pk_half2(v.x, v.y), pk_half2(v.z, v.w));
        }
        if (tid < TILEM) {
            const int* bp = bin + (size_t)(base + tid) * 8;
            int4 b0 = *(const int4*)bp;
            int4 b1 = *(const int4*)(bp + 4);
            int m = (b0.x != 0) | ((b0.y != 0) << 1) | ((b0.z != 0) << 2) | ((b0.w != 0) << 3)
                  | ((b1.x != 0) << 4) | ((b1.y != 0) << 5) | ((b1.z != 0) << 6) | ((b1.w != 0) << 7);
            smask[tid] = m;
            oct[base + tid] = (float)(m - 1);
        }
#pragma unroll
        for (int it = 0; it < 2; it++)
            wtail[it * NTHR + tid] = Wu1[4096 + it * NTHR + tid];
    }

    uint4 wr0, wr1, wr2, wr3;
    auto prefetchW = [&](int slot) {
        const uint4* sh = (const uint4*)(g_wh + slot * 4096);
        const uint4* sl = (const uint4*)(g_wl + slot * 4096);
        wr0 = sh[tid]; wr1 = sh[tid + 256];
        wr2 = sl[tid]; wr3 = sl[tid + 256];
    };
    auto commitW = [&](int buf) {
        char* b = smem + SM_W + buf * 18432;
        int i0 = tid, i1 = tid + 256;
        *(uint4*)(b + (i0 >> 3) * ARS + (i0 & 7) * 16)        = wr0;
        *(uint4*)(b + (i1 >> 3) * ARS + (i1 & 7) * 16)        = wr1;
        *(uint4*)(b + 9216 + (i0 >> 3) * ARS + (i0 & 7) * 16) = wr2;
        *(uint4*)(b + 9216 + (i1 >> 3) * ARS + (i1 & 7) * 16) = wr3;
    };

    uint32_t aoff = (uint32_t)((mrow + (lane & 7) + ((lane >> 3) & 1) * 8) * ARS
                              + ((lane >> 4) & 1) * 16);
    uint32_t woff = (uint32_t)((ncol + (lane & 7) + ((lane >> 4) & 1) * 8) * ARS
                              + ((lane >> 3) & 1) * 16);

    float acc[2][4][4];

    prefetchW(0);
    commitW(0);
    __syncthreads();          // prologue + W0 visible
    prefetchW(1);

    // ---- j0: h = prelu(X@Wd1+b) -> R1 fp16 ----
    zero_acc(acc);
    chain_gemm(sb + SM_R0 + aoff, sb + SM_W + woff, sb + SM_W + 9216 + woff, acc);
    add_bias(acc, 0, ncol, tg);
    apply_prelu(acc, 0, ncol, tg);
    store_f16(smem + SM_R1, acc, mrow, g, ncol, tg);
    __syncthreads();
    commitW(1);               // W_j1
    __syncthreads();
    prefetchW(2);

    // ---- j1: rec = X + h@Wd2 + b -> R0 ----
    zero_acc(acc);
    chain_gemm(sb + SM_R1 + aoff, sb + SM_W + 18432 + woff, sb + SM_W + 27648 + woff, acc);
    add_bias(acc, 1, ncol, tg);
    add_residual(smem + SM_R0, acc, mrow, g, ncol, tg);
    store_f16(smem + SM_R0, acc, mrow, g, ncol, tg);
    __syncthreads();
    commitW(0);               // W_j2
    __syncthreads();

    // ---- j2: p = prelu(rec@Wp1+b) -> R1 ----
    zero_acc(acc);
    chain_gemm(sb + SM_R0 + aoff, sb + SM_W + woff, sb + SM_W + 9216 + woff, acc);
    add_bias(acc, 2, ncol, tg);
    apply_prelu(acc, 2, ncol, tg);
    store_f16(smem + SM_R1, acc, mrow, g, ncol, tg);
    prefetchW(3);             // Wu1 for j7
    CP_WAIT(0);               // pred W chunks landed (long ago)
    __syncthreads();          // publish p + pred W

    // ---- pred group: A = p cached in registers; 4 sync-free chunks ----
    {
        uint32_t aC[4][2][4];
        uint32_t aR1 = sb + SM_R1 + aoff;
#pragma unroll
        for (int kc = 0; kc < 4; kc++) {
            ldm4(aC[kc][0], aR1 + kc * 32);
            ldm4(aC[kc][1], aR1 + kc * 32 + 16 * ARS);
        }
#pragma unroll
        for (int c = 0; c < 4; c++) {
            zero_acc(acc);
            heavy_gemm(aC, sb + SM_WX + c * 9216 + woff, acc);
            add_bias(acc, 3 + c, ncol, tg);
            int o0 = c * 64;
            bool evenr = ((g & 1) == 0);   // r parity == g parity; col always even
#pragma unroll
            for (int mt = 0; mt < 2; mt++) {
                int r = base + mrow + mt * 16 + g;
#pragma unroll
                for (int nt = 0; nt < 4; nt++) {
                    int col = o0 + ncol + nt * 8 + tg * 2;
                    float* cc = acc[mt][nt];
                    float* p0 = pred + (size_t)r * 255 + col;
                    float* p1 = pred + (size_t)(r + 8) * 255 + col;
                    if (col + 1 < 255) {
                        if (evenr) {
                            *(float2*)p0 = make_float2(cc[0], cc[1]);
                            *(float2*)p1 = make_float2(cc[2], cc[3]);
                        } else {
                            p0[0] = cc[0]; p0[1] = cc[1];
                            p1[0] = cc[2]; p1[1] = cc[3];
                        }
                    } else if (col < 255) {
                        p0[0] = cc[0]; p1[0] = cc[2];
                    }
                }
            }
        }
    }
    __syncthreads();          // all pred-W reads done (WAR for up4 staging)
    commitW(0);               // W_j7
    stage4(SM_WX, 4);         // async: up4 chunks 0-3 -> SM_WX (overlaps j7..j9)
    __syncthreads();
    prefetchW(4);

    // ---- j7: u1 = prelu([rec,bin]@Wu1+b) -> R1 ----
    zero_acc(acc);
    chain_gemm(sb + SM_R0 + aoff, sb + SM_W + woff, sb + SM_W + 9216 + woff, acc);
    add_bias(acc, 7, ncol, tg);
    {   // bin-concat tail (exact fp32)
#pragma unroll
        for (int mt = 0; mt < 2; mt++) {
            int rA = mrow + mt * 16 + g;
            int mA = smask[rA], mB = smask[rA + 8];
#pragma unroll
            for (int jj = 0; jj < 8; jj++) {
                bool bA = (mA >> jj) & 1, bB = (mB >> jj) & 1;
                if (bA | bB) {
#pragma unroll
                    for (int nt = 0; nt < 4; nt++) {
                        float2 t = *(const float2*)(wtail + jj * 64 + ncol + nt * 8 + tg * 2);
                        float* c = acc[mt][nt];
                        if (bA) { c[0] += 256.f * t.x; c[1] += 256.f * t.y; }
                        if (bB) { c[2] += 256.f * t.x; c[3] += 256.f * t.y; }
                    }
                }
            }
        }
    }
    apply_prelu(acc, 7, ncol, tg);
    store_f16(smem + SM_R1, acc, mrow, g, ncol, tg);
    __syncthreads();
    commitW(1);               // W_j8
    __syncthreads();
    prefetchW(5);

    // ---- j8: h2 = prelu(u1@Wu2+b) -> R0 (rec dead) ----
    zero_acc(acc);
    chain_gemm(sb + SM_R1 + aoff, sb + SM_W + 18432 + woff, sb + SM_W + 27648 + woff, acc);
    add_bias(acc, 8, ncol, tg);
    apply_prelu(acc, 8, ncol, tg);
    store_f16(smem + SM_R0, acc, mrow, g, ncol, tg);
    __syncthreads();
    commitW(0);               // W_j9
    __syncthreads();

    // ---- j9: u = u1 + h2@Wu3 + b -> R1 ----
    zero_acc(acc);
    chain_gemm(sb + SM_R0 + aoff, sb + SM_W + woff, sb + SM_W + 9216 + woff, acc);
    add_bias(acc, 9, ncol, tg);
    add_residual(smem + SM_R1, acc, mrow, g, ncol, tg);
    store_f16(smem + SM_R1, acc, mrow, g, ncol, tg);
    __syncthreads();          // u published; all chain-W reads done

    // async: up4 chunks 4-7 -> chain W region (dead), overlaps up4 chunks 0-3
    stage4(SM_W, 8);
    CP_WAIT(1);               // up4 chunks 0-3 complete (group issued earlier)
    __syncthreads();          // publish them

    // ---- up4 group: A = u cached in registers ----
    {
        uint32_t aC[4][2][4];
        uint32_t aR1 = sb + SM_R1 + aoff;
#pragma unroll
        for (int kc = 0; kc < 4; kc++) {
            ldm4(aC[kc][0], aR1 + kc * 32);
            ldm4(aC[kc][1], aR1 + kc * 32 + 16 * ARS);
        }
        auto up4_chunk = [&](int c, uint32_t wb) {
            zero_acc(acc);
            heavy_gemm(aC, wb + woff, acc);
            add_bias(acc, 10 + c, ncol, tg);
#pragma unroll
            for (int mt = 0; mt < 2; mt++) {
                int rA = mrow + mt * 16 + g;
                bool okA = (smask[rA] >> c) & 1, okB = (smask[rA + 8] >> c) & 1;
                int iA = okA ? __ldg(&g_inv[(size_t)(base + rA) * 8 + c]) : 0;
                int iB = okB ? __ldg(&g_inv[(size_t)(base + rA + 8) * 8 + c]) : 0;
#pragma unroll
                for (int nt = 0; nt < 4; nt++) {
                    int col = ncol + nt * 8 + tg * 2;
                    float* cc = acc[mt][nt];
                    if (okA) *(float2*)(newF + (size_t)iA * 64 + col) = make_float2(cc[0], cc[1]);
                    if (okB) *(float2*)(newF + (size_t)iB * 64 + col) = make_float2(cc[2], cc[3]);
                }
            }
        };
#pragma unroll
        for (int c = 0; c < 4; c++) up4_chunk(c, sb + SM_WX + c * 9216);
        CP_WAIT(0);           // up4 chunks 4-7 complete
        __syncthreads();      // publish
#pragma unroll
        for (int c = 4; c < 8; c++) up4_chunk(c, sb + SM_W + (c - 4) * 9216);
    }
}

extern "C" void kernel_launch(void* const* d_in, const int* in_sizes, int n_in,
                              void* d_out, int out_size) {
    const float* X   = (const float*)d_in[0];
    const int*   bin = (const int*)d_in[1];
    const int*   sel = (const int*)d_in[2];
    const float* Wd1 = (const float*)d_in[3];
    const float* bd1 = (const float*)d_in[4];
    const float* ad  = (const float*)d_in[5];
    const float* Wd2 = (const float*)d_in[6];
    const float* bd2 = (const float*)d_in[7];
    const float* Wp1 = (const float*)d_in[8];
    const float* bp1 = (const float*)d_in[9];
    const float* ap  = (const float*)d_in[10];
    const float* Wp2 = (const float*)d_in[11];
    const float* bp2 = (const float*)d_in[12];
    const float* Wu1 = (const float*)d_in[13];
    const float* bu1 = (const float*)d_in[14];
    const float* au1 = (const float*)d_in[15];
    const float* Wu2 = (const float*)d_in[16];
    const float* bu2 = (const float*)d_in[17];
    const float* au2 = (const float*)d_in[18];
    const float* Wu3 = (const float*)d_in[19];
    const float* bu3 = (const float*)d_in[20];
    const float* Wu4 = (const float*)d_in[21];
    const float* bu4 = (const float*)d_in[22];

    int n = in_sizes[0] / 64;
    int M = in_sizes[2];
    float* newF = (float*)d_out;
    float* pred = newF + (size_t)M * 64;
    float* oct  = pred + (size_t)n * 255;

    cudaFuncSetAttribute(k_main, cudaFuncAttributeMaxDynamicSharedMemorySize, SM_TOTAL);

    int inv_blocks = (M + 255) / 256;
    k_pre<<<72 + inv_blocks, 256>>>(Wd1, Wd2, Wp1, Wp2, Wu1, Wu2, Wu3, Wu4,
                                    bd1, bd2, bp1, bp2, bu1, bu2, bu3, bu4,
                                    ad, ap, au1, au2, sel, M);
    k_main<<<n / TILEM, NTHR, SM_TOTAL>>>(X, bin, Wu1, pred, oct, newF);
}

// round 15
// speedup vs baseline: 1.4364x; 1.1088x over previous
#include <cuda_runtime.h>
#include <cuda_bf16.h>
#include <cuda_fp16.h>
#include <cstdint>

#define TILEM 128
#define NTHR  256
#define ARS   144      // smem row stride (bytes)

// smem byte offsets
#define SM_R0    0
#define SM_R1    18432
#define SM_W     36864   // chain W double buffer: buf0@0, buf1@9216 (single-term)
#define SM_WX    55296   // heavy W region: 4 chunks x 9216
#define SM_WTAIL 92160
#define SM_MASK  94208
#define SM_TOTAL 94720

// chain weights (fp16 single, [n][k] 64x64), slots: 0=Wd1 1=Wd2 2=Wp1 3=Wu1 4=Wu2 5=Wu3
__device__ __align__(16) __half g_wc[6 * 4096];
// heavy weights (fp16 single, [n][k] 64x64), chunks: 0-3 = Wp2, 4-11 = Wu4
__device__ __align__(16) __half g_wx[12 * 4096];
__device__ __align__(16) float g_bb[18 * 64];
__device__ __align__(16) float g_aw[18 * 64];
__device__ int g_inv[(size_t)262144 * 8];

static __device__ __forceinline__ uint32_t smem_u32(const void* p) {
    uint32_t a;
    asm("{ .reg .u64 t; cvta.to.shared.u64 t, %1; cvt.u32.u64 %0, t; }" : "=r"(a) : "l"(p));
    return a;
}
static __device__ __forceinline__ uint32_t pk_half2(float a, float b) {
    __half2 t = __floats2half2_rn(a, b);
    return *(uint32_t*)&t;
}
static __device__ __forceinline__ float2 upk_half2(uint32_t u) {
    return __half22float2(*(__half2*)&u);
}
static __device__ __forceinline__ void mma_f16(float* c, const uint32_t* a, const uint32_t* b) {
    asm volatile(
        "mma.sync.aligned.m16n8k16.row.col.f32.f16.f16.f32 "
        "{%0,%1,%2,%3}, {%4,%5,%6,%7}, {%8,%9}, {%0,%1,%2,%3};"
        : "+f"(c[0]), "+f"(c[1]), "+f"(c[2]), "+f"(c[3])
        : "r"(a[0]), "r"(a[1]), "r"(a[2]), "r"(a[3]), "r"(b[0]), "r"(b[1]));
}
static __device__ __forceinline__ void ldm4(uint32_t* r, uint32_t addr) {
    asm volatile("ldmatrix.sync.aligned.m8n8.x4.shared.b16 {%0,%1,%2,%3}, [%4];"
        : "=r"(r[0]), "=r"(r[1]), "=r"(r[2]), "=r"(r[3]) : "r"(addr));
}
static __device__ __forceinline__ void cpa16(uint32_t dst, const void* src) {
    asm volatile("cp.async.cg.shared.global [%0], [%1], 16;" :: "r"(dst), "l"(src));
}
#define CP_COMMIT() asm volatile("cp.async.commit_group;" ::: "memory")
#define CP_WAIT(n)  asm volatile("cp.async.wait_group %0;" :: "n"(n) : "memory")

static __device__ __forceinline__ void zero_acc(float acc[2][4][4]) {
#pragma unroll
    for (int mt = 0; mt < 2; mt++)
#pragma unroll
        for (int nt = 0; nt < 4; nt++)
#pragma unroll
            for (int i = 0; i < 4; i++) acc[mt][nt][i] = 0.f;
}

// GEMM: A single fp16 from smem, W single fp16 from smem; warp tile m32 x n32
static __device__ __forceinline__ void chain_gemm(uint32_t aB, uint32_t wb, float acc[2][4][4]) {
#pragma unroll
    for (int kc = 0; kc < 4; kc++) {
        uint32_t ko = kc * 32;
        uint32_t a2[2][4], bh[2][4];
        ldm4(a2[0], aB + ko); ldm4(a2[1], aB + ko + 16 * ARS);
        ldm4(bh[0], wb + ko); ldm4(bh[1], wb + ko + 16 * ARS);
#pragma unroll
        for (int p2 = 0; p2 < 2; p2++)
#pragma unroll
            for (int h = 0; h < 2; h++) {
                int nt = p2 * 2 + h;
                const uint32_t* Bh = &bh[p2][h * 2];
#pragma unroll
                for (int mt = 0; mt < 2; mt++)
                    mma_f16(acc[mt][nt], a2[mt], Bh);
            }
    }
}
// heavy GEMM: A cached in registers, W single fp16 from smem
static __device__ __forceinline__ void heavy_gemm(const uint32_t aC[4][2][4], uint32_t wb,
                                                  float acc[2][4][4]) {
#pragma unroll
    for (int kc = 0; kc < 4; kc++) {
        uint32_t ko = kc * 32;
        uint32_t bh[2][4];
        ldm4(bh[0], wb + ko); ldm4(bh[1], wb + ko + 16 * ARS);
#pragma unroll
        for (int p2 = 0; p2 < 2; p2++)
#pragma unroll
            for (int h = 0; h < 2; h++) {
                int nt = p2 * 2 + h;
                const uint32_t* Bh = &bh[p2][h * 2];
#pragma unroll
                for (int mt = 0; mt < 2; mt++)
                    mma_f16(acc[mt][nt], aC[kc][mt], Bh);
            }
    }
}

static __device__ __forceinline__ void add_bias(float acc[2][4][4], int j, int ncol, int tg) {
    const float* bb = g_bb + j * 64;
#pragma unroll
    for (int nt = 0; nt < 4; nt++) {
        float2 bv = __ldg((const float2*)(bb + ncol + nt * 8 + tg * 2));
#pragma unroll
        for (int mt = 0; mt < 2; mt++) {
            float* c = acc[mt][nt];
            c[0] += bv.x; c[1] += bv.y; c[2] += bv.x; c[3] += bv.y;
        }
    }
}
static __device__ __forceinline__ void apply_prelu(float acc[2][4][4], int j, int ncol, int tg) {
    const float* aw = g_aw + j * 64;
#pragma unroll
    for (int nt = 0; nt < 4; nt++) {
        float2 av = __ldg((const float2*)(aw + ncol + nt * 8 + tg * 2));
#pragma unroll
        for (int mt = 0; mt < 2; mt++) {
            float* c = acc[mt][nt];
            c[0] = c[0] >= 0.f ? c[0] : av.x * c[0];
            c[1] = c[1] >= 0.f ? c[1] : av.y * c[1];
            c[2] = c[2] >= 0.f ? c[2] : av.x * c[2];
            c[3] = c[3] >= 0.f ? c[3] : av.y * c[3];
        }
    }
}
static __device__ __forceinline__ void add_residual(const char* rgn, float acc[2][4][4],
                                                    int mrow, int g, int ncol, int tg) {
#pragma unroll
    for (int mt = 0; mt < 2; mt++) {
        int r = mrow + mt * 16 + g;
#pragma unroll
        for (int nt = 0; nt < 4; nt++) {
            uint32_t off0 = r * ARS + (ncol + nt * 8 + tg * 2) * 2;
            uint32_t off1 = off0 + 8 * ARS;
            float2 v0 = upk_half2(*(const uint32_t*)(rgn + off0));
            float2 v1 = upk_half2(*(const uint32_t*)(rgn + off1));
            float* c = acc[mt][nt];
            c[0] += v0.x; c[1] += v0.y; c[2] += v1.x; c[3] += v1.y;
        }
    }
}
static __device__ __forceinline__ void store_f16(char* dst, float acc[2][4][4],
                                                 int mrow, int g, int ncol, int tg) {
#pragma unroll
    for (int mt = 0; mt < 2; mt++) {
        int r = mrow + mt * 16 + g;
#pragma unroll
        for (int nt = 0; nt < 4; nt++) {
            uint32_t off0 = r * ARS + (ncol + nt * 8 + tg * 2) * 2;
            uint32_t off1 = off0 + 8 * ARS;
            float* c = acc[mt][nt];
            *(uint32_t*)(dst + off0) = pk_half2(c[0], c[1]);
            *(uint32_t*)(dst + off1) = pk_half2(c[2], c[3]);
        }
    }
}

// ---------------- K_pre: merged weight-split (72 blocks) + inverse map (rest) ----------------
__global__ void k_pre(const float* __restrict__ Wd1, const float* __restrict__ Wd2,
                      const float* __restrict__ Wp1, const float* __restrict__ Wp2,
                      const float* __restrict__ Wu1, const float* __restrict__ Wu2,
                      const float* __restrict__ Wu3, const float* __restrict__ Wu4,
                      const float* __restrict__ bd1, const float* __restrict__ bd2,
                      const float* __restrict__ bp1, const float* __restrict__ bp2,
                      const float* __restrict__ bu1, const float* __restrict__ bu2,
                      const float* __restrict__ bu3, const float* __restrict__ bu4,
                      const float* __restrict__ ad,  const float* __restrict__ ap_,
                      const float* __restrict__ au1, const float* __restrict__ au2,
                      const int* __restrict__ sel, int M) {
    int b = blockIdx.x;
    if (b >= 72) {   // inverse-map blocks
        int m = (b - 72) * 256 + threadIdx.x;
        if (m < M) g_inv[sel[m]] = m;
        return;
    }
    int j = b >> 2;
    int slot = (j == 0) ? 0 : (j == 1) ? 1 : (j == 2) ? 2 :
               (j == 7) ? 3 : (j == 8) ? 4 : (j == 9) ? 5 : -1;
    {
        int t0 = (b & 3) * 1024;
#pragma unroll
        for (int it = 0; it < 4; it++) {
            int t = t0 + it * 256 + threadIdx.x;
            int n = t >> 6, k = t & 63;
            float v;
            if (j == 0)      v = Wd1[k * 64 + n];
            else if (j == 1) v = Wd2[k * 64 + n];
            else if (j == 2) v = Wp1[k * 64 + n];
            else if (j <= 6) { int ng = (j - 3) * 64 + n; v = (ng < 255) ? Wp2[k * 255 + ng] : 0.f; }
            else if (j == 7) v = Wu1[k * 64 + n];
            else if (j == 8) v = Wu2[k * 64 + n];
            else if (j == 9) v = Wu3[k * 64 + n];
            else             v = Wu4[(size_t)k * 512 + (j - 10) * 64 + n];
            if (slot >= 0) {
                g_wc[slot * 4096 + t] = __float2half(v);
            } else {
                int ch = (j <= 6) ? (j - 3) : (4 + j - 10);
                g_wx[ch * 4096 + n * 64 + k] = __float2half(v);
            }
        }
    }
    if ((b & 3) == 0 && threadIdx.x < 64) {
        int c = threadIdx.x; float bv = 0.f, a = 0.f;
        switch (j) {
            case 0: bv = bd1[c]; a = ad[c]; break;
            case 1: bv = bd2[c]; break;
            case 2: bv = bp1[c]; a = ap_[c]; break;
            case 3: case 4: case 5: case 6: {
                int ng = (j - 3) * 64 + c; bv = (ng < 255) ? bp2[ng] : 0.f; break; }
            case 7: bv = bu1[c]; a = au1[c]; break;
            case 8: bv = bu2[c]; a = au2[c]; break;
            case 9: bv = bu3[c]; break;
            default: bv = bu4[(j - 10) * 64 + c]; break;
        }
        g_bb[j * 64 + c] = bv;
        g_aw[j * 64 + c] = a;
    }
}

// ---------------- fused main kernel ----------------
__global__ __launch_bounds__(NTHR, 2)
void k_main(const float* __restrict__ X, const int* __restrict__ bin,
            const float* __restrict__ Wu1,
            float* __restrict__ pred, float* __restrict__ oct, float* __restrict__ newF) {
    extern __shared__ char smem[];
    const uint32_t sb = smem_u32(smem);
    int tid = threadIdx.x;
    int wid = tid >> 5, lane = tid & 31;
    int g = lane >> 2, tg = lane & 3;
    int mrow = (wid >> 1) * 32;
    int ncol = (wid & 1) * 32;
    int base = blockIdx.x * TILEM;

    float* wtail = (float*)(smem + SM_WTAIL);
    int*   smask = (int*)(smem + SM_MASK);

    // async-stage 4 heavy chunks into contiguous region
    auto stage4 = [&](uint32_t region, int ch0) {
#pragma unroll
        for (int it = 0; it < 8; it++) {
            int i = it * NTHR + tid;
            int c = i >> 9, w = i & 511;
            cpa16(sb + region + c * 9216 + (w >> 3) * ARS + (w & 7) * 16,
                  g_wx + (size_t)(ch0 + c) * 4096 + (size_t)w * 8);
        }
        CP_COMMIT();
    };
    // async-stage up4 chunks 4-7: chunks 0,1 -> R0, chunks 2,3 -> chain W region
    auto stage4_split = [&]() {
#pragma unroll
        for (int it = 0; it < 8; it++) {
            int i = it * NTHR + tid;
            int c = i >> 9, w = i & 511;
            uint32_t dst = (c < 2) ? (uint32_t)(SM_R0 + c * 9216)
                                   : (uint32_t)(SM_W + (c - 2) * 9216);
            cpa16(sb + dst + (w >> 3) * ARS + (w & 7) * 16,
                  g_wx + (size_t)(8 + c) * 4096 + (size_t)w * 8);
        }
        CP_COMMIT();
    };

    // ---- issue pred W (chunks 0-3 -> SM_WX) immediately ----
    stage4(SM_WX, 0);

    // ---- prologue: X -> R0 fp16, mask/oct, wtail ----
    {
        const float4* Xr = (const float4*)(X + (size_t)base * 64);
#pragma unroll
        for (int it = 0; it < 8; it++) {
            int idx = it * NTHR + tid;
            int row = idx >> 4, q = idx & 15;
            float4 v = Xr[idx];
            *(uint2*)(smem + SM_R0 + row * ARS + q * 8) =
                make_uint2(pk_half2(v.x, v.y), pk_half2(v.z, v.w));
        }
        if (tid < TILEM) {
            const int* bp = bin + (size_t)(base + tid) * 8;
            int4 b0 = *(const int4*)bp;
            int4 b1 = *(const int4*)(bp + 4);
            int m = (b0.x != 0) | ((b0.y != 0) << 1) | ((b0.z != 0) << 2) | ((b0.w != 0) << 3)
                  | ((b1.x != 0) << 4) | ((b1.y != 0) << 5) | ((b1.z != 0) << 6) | ((b1.w != 0) << 7);
            smask[tid] = m;
            oct[base + tid] = (float)(m - 1);
        }
#pragma unroll
        for (int it = 0; it < 2; it++)
            wtail[it * NTHR + tid] = Wu1[4096 + it * NTHR + tid];
    }

    uint4 wr0, wr1;
    auto prefetchW = [&](int slot) {
        const uint4* sh = (const uint4*)(g_wc + slot * 4096);
        wr0 = sh[tid]; wr1 = sh[tid + 256];
    };
    auto commitW = [&](int buf) {
        char* b = smem + SM_W + buf * 9216;
        int i0 = tid, i1 = tid + 256;
        *(uint4*)(b + (i0 >> 3) * ARS + (i0 & 7) * 16) = wr0;
        *(uint4*)(b + (i1 >> 3) * ARS + (i1 & 7) * 16) = wr1;
    };

    uint32_t aoff = (uint32_t)((mrow + (lane & 7) + ((lane >> 3) & 1) * 8) * ARS
                              + ((lane >> 4) & 1) * 16);
    uint32_t woff = (uint32_t)((ncol + (lane & 7) + ((lane >> 4) & 1) * 8) * ARS
                              + ((lane >> 3) & 1) * 16);

    float acc[2][4][4];

    prefetchW(0);
    commitW(0);
    __syncthreads();          // prologue + W0 visible
    prefetchW(1);

    // ---- j0: h = prelu(X@Wd1+b) -> R1 fp16 ----
    zero_acc(acc);
    chain_gemm(sb + SM_R0 + aoff, sb + SM_W + woff, acc);
    add_bias(acc, 0, ncol, tg);
    apply_prelu(acc, 0, ncol, tg);
    store_f16(smem + SM_R1, acc, mrow, g, ncol, tg);
    __syncthreads();
    commitW(1);               // W_j1
    __syncthreads();
    prefetchW(2);

    // ---- j1: rec = X + h@Wd2 + b -> R0 ----
    zero_acc(acc);
    chain_gemm(sb + SM_R1 + aoff, sb + SM_W + 9216 + woff, acc);
    add_bias(acc, 1, ncol, tg);
    add_residual(smem + SM_R0, acc, mrow, g, ncol, tg);
    store_f16(smem + SM_R0, acc, mrow, g, ncol, tg);
    __syncthreads();
    commitW(0);               // W_j2
    __syncthreads();

    // ---- j2: p = prelu(rec@Wp1+b) -> R1 ----
    zero_acc(acc);
    chain_gemm(sb + SM_R0 + aoff, sb + SM_W + woff, acc);
    add_bias(acc, 2, ncol, tg);
    apply_prelu(acc, 2, ncol, tg);
    store_f16(smem + SM_R1, acc, mrow, g, ncol, tg);
    prefetchW(3);             // Wu1 for j7
    CP_WAIT(0);               // pred W chunks landed
    __syncthreads();          // publish p + pred W

    // ---- pred group: A = p cached in registers; 4 sync-free chunks ----
    {
        uint32_t aC[4][2][4];
        uint32_t aR1 = sb + SM_R1 + aoff;
#pragma unroll
        for (int kc = 0; kc < 4; kc++) {
            ldm4(aC[kc][0], aR1 + kc * 32);
            ldm4(aC[kc][1], aR1 + kc * 32 + 16 * ARS);
        }
#pragma unroll
        for (int c = 0; c < 4; c++) {
            zero_acc(acc);
            heavy_gemm(aC, sb + SM_WX + c * 9216 + woff, acc);
            add_bias(acc, 3 + c, ncol, tg);
            int o0 = c * 64;
            bool evenr = ((g & 1) == 0);   // r parity == g parity; col always even
#pragma unroll
            for (int mt = 0; mt < 2; mt++) {
                int r = base + mrow + mt * 16 + g;
#pragma unroll
                for (int nt = 0; nt < 4; nt++) {
                    int col = o0 + ncol + nt * 8 + tg * 2;
                    float* cc = acc[mt][nt];
                    float* p0 = pred + (size_t)r * 255 + col;
                    float* p1 = pred + (size_t)(r + 8) * 255 + col;
                    if (col + 1 < 255) {
                        if (evenr) {
                            *(float2*)p0 = make_float2(cc[0], cc[1]);
                            *(float2*)p1 = make_float2(cc[2], cc[3]);
                        } else {
                            p0[0] = cc[0]; p0[1] = cc[1];
                            p1[0] = cc[2]; p1[1] = cc[3];
                        }
                    } else if (col < 255) {
                        p0[0] = cc[0]; p1[0] = cc[2];
                    }
                }
            }
        }
    }
    __syncthreads();          // pred-W reads done (WAR for up4 staging into WX)
    commitW(0);               // W_j7
    stage4(SM_WX, 4);         // async: up4 chunks 0-3 -> SM_WX (overlaps j7..j9)
    __syncthreads();
    prefetchW(4);

    // ---- j7: u1 = prelu([rec,bin]@Wu1+b) -> R1 ----
    zero_acc(acc);
    chain_gemm(sb + SM_R0 + aoff, sb + SM_W + woff, acc);
    add_bias(acc, 7, ncol, tg);
    {   // bin-concat tail (exact fp32)
#pragma unroll
        for (int mt = 0; mt < 2; mt++) {
            int rA = mrow + mt * 16 + g;
            int mA = smask[rA], mB = smask[rA + 8];
#pragma unroll
            for (int jj = 0; jj < 8; jj++) {
                bool bA = (mA >> jj) & 1, bB = (mB >> jj) & 1;
                if (bA | bB) {
#pragma unroll
                    for (int nt = 0; nt < 4; nt++) {
                        float2 t = *(const float2*)(wtail + jj * 64 + ncol + nt * 8 + tg * 2);
                        float* c = acc[mt][nt];
                        if (bA) { c[0] += 256.f * t.x; c[1] += 256.f * t.y; }
                        if (bB) { c[2] += 256.f * t.x; c[3] += 256.f * t.y; }
                    }
                }
            }
        }
    }
    apply_prelu(acc, 7, ncol, tg);
    store_f16(smem + SM_R1, acc, mrow, g, ncol, tg);
    __syncthreads();
    commitW(1);               // W_j8
    __syncthreads();
    prefetchW(5);

    // ---- j8: h2 = prelu(u1@Wu2+b) -> R0 (rec dead) ----
    zero_acc(acc);
    chain_gemm(sb + SM_R1 + aoff, sb + SM_W + 9216 + woff, acc);
    add_bias(acc, 8, ncol, tg);
    apply_prelu(acc, 8, ncol, tg);
    store_f16(smem + SM_R0, acc, mrow, g, ncol, tg);
    __syncthreads();
    commitW(0);               // W_j9
    __syncthreads();

    // ---- j9: u = u1 + h2@Wu3 + b -> R1 ----
    zero_acc(acc);
    chain_gemm(sb + SM_R0 + aoff, sb + SM_W + woff, acc);
    add_bias(acc, 9, ncol, tg);
    add_residual(smem + SM_R1, acc, mrow, g, ncol, tg);
    store_f16(smem + SM_R1, acc, mrow, g, ncol, tg);
    __syncthreads();          // u published; chain-W + R0 reads done

    // async: up4 chunks 4-7 -> R0 + chain W region (both dead), overlaps chunks 0-3
    stage4_split();
    CP_WAIT(1);               // up4 chunks 0-3 complete
    __syncthreads();          // publish

    // ---- up4 group: A = u cached in registers ----
    {
        uint32_t aC[4][2][4];
        uint32_t aR1 = sb + SM_R1 + aoff;
#pragma unroll
        for (int kc = 0; kc < 4; kc++) {
            ldm4(aC[kc][0], aR1 + kc * 32);
            ldm4(aC[kc][1], aR1 + kc * 32 + 16 * ARS);
        }
        auto up4_chunk = [&](int c, uint32_t wb) {
            zero_acc(acc);
            heavy_gemm(aC, wb + woff, acc);
            add_bias(acc, 10 + c, ncol, tg);
#pragma unroll
            for (int mt = 0; mt < 2; mt++) {
                int rA = mrow + mt * 16 + g;
                bool okA = (smask[rA] >> c) & 1, okB = (smask[rA + 8] >> c) & 1;
                int iA = okA ? __ldg(&g_inv[(size_t)(base + rA) * 8 + c]) : 0;
                int iB = okB ? __ldg(&g_inv[(size_t)(base + rA + 8) * 8 + c]) : 0;
#pragma unroll
                for (int nt = 0; nt < 4; nt++) {
                    int col = ncol + nt * 8 + tg * 2;
                    float* cc = acc[mt][nt];
                    if (okA) *(float2*)(newF + (size_t)iA * 64 + col) = make_float2(cc[0], cc[1]);
                    if (okB) *(float2*)(newF + (size_t)iB * 64 + col) = make_float2(cc[2], cc[3]);
                }
            }
        };
#pragma unroll
        for (int c = 0; c < 4; c++) up4_chunk(c, sb + SM_WX + c * 9216);
        CP_WAIT(0);           // up4 chunks 4-7 complete
        __syncthreads();      // publish
        up4_chunk(4, sb + SM_R0);
        up4_chunk(5, sb + SM_R0 + 9216);
        up4_chunk(6, sb + SM_W);
        up4_chunk(7, sb + SM_W + 9216);
    }
}

extern "C" void kernel_launch(void* const* d_in, const int* in_sizes, int n_in,
                              void* d_out, int out_size) {
    const float* X   = (const float*)d_in[0];
    const int*   bin = (const int*)d_in[1];
    const int*   sel = (const int*)d_in[2];
    const float* Wd1 = (const float*)d_in[3];
    const float* bd1 = (const float*)d_in[4];
    const float* ad  = (const float*)d_in[5];
    const float* Wd2 = (const float*)d_in[6];
    const float* bd2 = (const float*)d_in[7];
    const float* Wp1 = (const float*)d_in[8];
    const float* bp1 = (const float*)d_in[9];
    const float* ap  = (const float*)d_in[10];
    const float* Wp2 = (const float*)d_in[11];
    const float* bp2 = (const float*)d_in[12];
    const float* Wu1 = (const float*)d_in[13];
    const float* bu1 = (const float*)d_in[14];
    const float* au1 = (const float*)d_in[15];
    const float* Wu2 = (const float*)d_in[16];
    const float* bu2 = (const float*)d_in[17];
    const float* au2 = (const float*)d_in[18];
    const float* Wu3 = (const float*)d_in[19];
    const float* bu3 = (const float*)d_in[20];
    const float* Wu4 = (const float*)d_in[21];
    const float* bu4 = (const float*)d_in[22];

    int n = in_sizes[0] / 64;
    int M = in_sizes[2];
    float* newF = (float*)d_out;
    float* pred = newF + (size_t)M * 64;
    float* oct  = pred + (size_t)n * 255;

    cudaFuncSetAttribute(k_main, cudaFuncAttributeMaxDynamicSharedMemorySize, SM_TOTAL);

    int inv_blocks = (M + 255) / 256;
    k_pre<<<72 + inv_blocks, 256>>>(Wd1, Wd2, Wp1, Wp2, Wu1, Wu2, Wu3, Wu4,
                                    bd1, bd2, bp1, bp2, bu1, bu2, bu3, bu4,
                                    ad, ap, au1, au2, sel, M);
    k_main<<<n / TILEM, NTHR, SM_TOTAL>>>(X, bin, Wu1, pred, oct, newF);
}